// round 7
// baseline (speedup 1.0000x reference)
#include <cuda_runtime.h>
#include <cuda_bf16.h>

#define BB 16
#define NN 8192
#define SS 1024
#define KK 32
#define FULLMASK 0xFFFFFFFFu
typedef unsigned long long ull;

// ---------------- scratch (no allocs allowed) ----------------
__device__ float  g_newxyz[BB * SS * 3];   // FPS-selected centers
__device__ float  g_gmax[BB * SS * 3];     // max over K of diff, per coord
__device__ float  g_gsum[BB * SS * 3];     // sum over K of diff, per coord
__device__ double g_acc[2];                // sum(diff), sum(diff^2) for global std
__device__ float  g_lc[BB * 6 * SS];       // pooled features
__device__ float  g_ppts[BB * NN * 3];     // Morton-permuted coords
__device__ unsigned short g_oidxT[BB * NN];// per-thread-transposed orig indices
__device__ float4 g_ctr[BB * 32];          // region centroid + padded radius

// ---------------- f32x2 helpers (Blackwell packed fp32) ----------------
__device__ __forceinline__ ull pk2(float lo, float hi) {
    ull r;
    asm("mov.b64 %0, {%1, %2};" : "=l"(r) : "f"(lo), "f"(hi));
    return r;
}
__device__ __forceinline__ void upk2(float& lo, float& hi, ull v) {
    asm("mov.b64 {%0, %1}, %2;" : "=f"(lo), "=f"(hi) : "l"(v));
}
__device__ __forceinline__ ull add2(ull a, ull b) {
    ull r;
    asm("add.rn.f32x2 %0, %1, %2;" : "=l"(r) : "l"(a), "l"(b));
    return r;
}
__device__ __forceinline__ ull mul2(ull a, ull b) {
    ull r;
    asm("mul.rn.f32x2 %0, %1, %2;" : "=l"(r) : "l"(a), "l"(b));
    return r;
}

// =====================================================================
// K0: setup — bbox, Morton codes, bitonic sort, permuted coords, region
// centroid+radius (padded). Order only affects FPS pruning efficiency,
// never correctness.
// =====================================================================
__device__ __forceinline__ unsigned expand10(unsigned v) {
    v &= 1023u;
    v = (v | (v << 16)) & 0x030000FFu;
    v = (v | (v << 8))  & 0x0300F00Fu;
    v = (v | (v << 4))  & 0x030C30C3u;
    v = (v | (v << 2))  & 0x09249249u;
    return v;
}

__global__ void __launch_bounds__(1024) setup_kernel(const float* __restrict__ xyz)
{
    extern __shared__ ull skeys[];              // [NN] 64KB
    __shared__ float s_bb[6][32];
    __shared__ float s_box[6];
    const int b = blockIdx.x, t = threadIdx.x;
    const int lane = t & 31, warp = t >> 5;
    const float* X = xyz + (size_t)b * NN * 3;

    float mnx = 1e30f, mny = 1e30f, mnz = 1e30f;
    float mxx = -1e30f, mxy = -1e30f, mxz = -1e30f;
    float xs[8], ys[8], zs[8];
#pragma unroll
    for (int i = 0; i < 8; i++) {
        int p = t + (i << 10);
        float x = X[p * 3], y = X[p * 3 + 1], z = X[p * 3 + 2];
        xs[i] = x; ys[i] = y; zs[i] = z;
        mnx = fminf(mnx, x); mxx = fmaxf(mxx, x);
        mny = fminf(mny, y); mxy = fmaxf(mxy, y);
        mnz = fminf(mnz, z); mxz = fmaxf(mxz, z);
    }
#pragma unroll
    for (int o = 16; o; o >>= 1) {
        mnx = fminf(mnx, __shfl_xor_sync(FULLMASK, mnx, o));
        mny = fminf(mny, __shfl_xor_sync(FULLMASK, mny, o));
        mnz = fminf(mnz, __shfl_xor_sync(FULLMASK, mnz, o));
        mxx = fmaxf(mxx, __shfl_xor_sync(FULLMASK, mxx, o));
        mxy = fmaxf(mxy, __shfl_xor_sync(FULLMASK, mxy, o));
        mxz = fmaxf(mxz, __shfl_xor_sync(FULLMASK, mxz, o));
    }
    if (lane == 0) {
        s_bb[0][warp] = mnx; s_bb[1][warp] = mny; s_bb[2][warp] = mnz;
        s_bb[3][warp] = mxx; s_bb[4][warp] = mxy; s_bb[5][warp] = mxz;
    }
    __syncthreads();
    if (warp == 0) {
        float v0 = s_bb[0][lane], v1 = s_bb[1][lane], v2 = s_bb[2][lane];
        float v3 = s_bb[3][lane], v4 = s_bb[4][lane], v5 = s_bb[5][lane];
#pragma unroll
        for (int o = 16; o; o >>= 1) {
            v0 = fminf(v0, __shfl_xor_sync(FULLMASK, v0, o));
            v1 = fminf(v1, __shfl_xor_sync(FULLMASK, v1, o));
            v2 = fminf(v2, __shfl_xor_sync(FULLMASK, v2, o));
            v3 = fmaxf(v3, __shfl_xor_sync(FULLMASK, v3, o));
            v4 = fmaxf(v4, __shfl_xor_sync(FULLMASK, v4, o));
            v5 = fmaxf(v5, __shfl_xor_sync(FULLMASK, v5, o));
        }
        if (lane == 0) {
            s_box[0] = v0; s_box[1] = v1; s_box[2] = v2;
            s_box[3] = v3; s_box[4] = v4; s_box[5] = v5;
        }
    }
    __syncthreads();
    const float bx = s_box[0], by = s_box[1], bz = s_box[2];
    const float fx = 1023.0f / fmaxf(s_box[3] - bx, 1e-20f);
    const float fy = 1023.0f / fmaxf(s_box[4] - by, 1e-20f);
    const float fz = 1023.0f / fmaxf(s_box[5] - bz, 1e-20f);

#pragma unroll
    for (int i = 0; i < 8; i++) {
        int p = t + (i << 10);
        unsigned qx = (unsigned)fminf(fmaxf((xs[i] - bx) * fx, 0.f), 1023.f);
        unsigned qy = (unsigned)fminf(fmaxf((ys[i] - by) * fy, 0.f), 1023.f);
        unsigned qz = (unsigned)fminf(fmaxf((zs[i] - bz) * fz, 0.f), 1023.f);
        unsigned code = expand10(qx) | (expand10(qy) << 1) | (expand10(qz) << 2);
        skeys[p] = ((ull)code << 13) | (unsigned)p;
    }
    __syncthreads();

    // bitonic sort ascending, 4096 pairs / 1024 threads per stage
    for (int k = 2; k <= NN; k <<= 1) {
        for (int j = k >> 1; j > 0; j >>= 1) {
#pragma unroll
            for (int m = 0; m < 4; m++) {
                int pi = t + (m << 10);
                int i0 = ((pi & ~(j - 1)) << 1) | (pi & (j - 1));
                int i1 = i0 | j;
                ull a = skeys[i0], c = skeys[i1];
                bool up = ((i0 & k) == 0);
                if ((a > c) == up) { skeys[i0] = c; skeys[i1] = a; }
            }
            __syncthreads();
        }
    }

    // permuted outputs + per-warp region stats (region = 256 consecutive)
    float px[8], py[8], pz[8];
    float sx = 0.f, sy = 0.f, sz = 0.f;
#pragma unroll
    for (int i = 0; i < 8; i++) {
        int j = warp * 256 + i * 32 + lane;
        int o = (int)(skeys[j] & 0x1FFFull);
        float x = X[o * 3], y = X[o * 3 + 1], z = X[o * 3 + 2];
        px[i] = x; py[i] = y; pz[i] = z;
        float* dst = g_ppts + ((size_t)b * NN + j) * 3;
        dst[0] = x; dst[1] = y; dst[2] = z;
        g_oidxT[((size_t)b * 1024 + t) * 8 + i] = (unsigned short)o;
        sx += x; sy += y; sz += z;
    }
#pragma unroll
    for (int o = 16; o; o >>= 1) {
        sx += __shfl_xor_sync(FULLMASK, sx, o);
        sy += __shfl_xor_sync(FULLMASK, sy, o);
        sz += __shfl_xor_sync(FULLMASK, sz, o);
    }
    float cxm = sx * (1.0f / 256.0f), cym = sy * (1.0f / 256.0f), czm = sz * (1.0f / 256.0f);
    float md2 = 0.f;
#pragma unroll
    for (int i = 0; i < 8; i++) {
        float dx = px[i] - cxm, dy = py[i] - cym, dz = pz[i] - czm;
        md2 = fmaxf(md2, dx * dx + dy * dy + dz * dz);
    }
#pragma unroll
    for (int o = 16; o; o >>= 1)
        md2 = fmaxf(md2, __shfl_xor_sync(FULLMASK, md2, o));
    if (lane == 0) {
        float r = sqrtf(md2) * 1.001f + 1e-6f;   // padded radius
        g_ctr[b * 32 + warp] = make_float4(cxm, cym, czm, r);
    }
}

// =====================================================================
// K1: FPS with region pruning. 16 blocks x 1024 threads; warp owns 256
// Morton-consecutive points (8 slots/thread, f32x2-packed pairs). Exact
// reference math for distances (bitwise identical to scalar rn ops).
// Skip test: t2 > thr, thr = (r + sqrt(ub))^2 * 1.001 (cached) — skipped
// updates are provably no-ops, so results are bit-identical. Cached
// (max, min-orig-idx) per region stays exact across skips. Tie-break
// always by ORIGINAL index.
// =====================================================================
__global__ void __launch_bounds__(1024) fps_kernel(const float* __restrict__ xyz)
{
    const int b = blockIdx.x;
    const int t = threadIdx.x;
    const int lane = t & 31, warp = t >> 5;
    const float* X = xyz + (size_t)b * NN * 3;
    const float* P = g_ppts + (size_t)b * NN * 3;

    // 8 slots: position warp*256 + slot*32 + lane; pairs (2i,2i+1) packed
    ull px2[4], py2[4], pz2[4];
    float dist[8];
    const int base = warp * 256 + lane;
#pragma unroll
    for (int i = 0; i < 4; i++) {
        int p0 = base + (2 * i) * 32;
        int p1 = base + (2 * i + 1) * 32;
        px2[i] = pk2(P[p0 * 3 + 0], P[p1 * 3 + 0]);
        py2[i] = pk2(P[p0 * 3 + 1], P[p1 * 3 + 1]);
        pz2[i] = pk2(P[p0 * 3 + 2], P[p1 * 3 + 2]);
        dist[2 * i] = 1e10f;
        dist[2 * i + 1] = 1e10f;
    }
    // original indices of this thread's 8 slots (8 x u16 = 16B)
    const ulonglong2 o2 = *reinterpret_cast<const ulonglong2*>(
        g_oidxT + ((size_t)b * 1024 + t) * 8);
    const float4 cr = g_ctr[b * 32 + warp];
    const float gx = cr.x, gy = cr.y, gz = cr.z, gr = cr.w;

    unsigned regval = __float_as_uint(1e10f);   // cached region max (bits)
    unsigned regidx = 0;                        // cached argmax orig idx
    float    thr    = 3.0e38f;                  // never skip before 1st process

    __shared__ unsigned s_val[2][32];
    __shared__ unsigned s_idx[2][32];

    if (t == 0 && b == 0) { g_acc[0] = 0.0; g_acc[1] = 0.0; }  // reset per replay
    float cx = X[0], cy = X[1], cz = X[2];     // sample 0 = point 0
    if (t == 0) {
        float* o = g_newxyz + (size_t)(b * SS) * 3;
        o[0] = cx; o[1] = cy; o[2] = cz;
    }

    for (int s = 0; s < SS - 1; s++) {
        // region bound (warp-uniform; any rounding — margins are in thr)
        float tx = cx - gx, ty = cy - gy, tz = cz - gz;
        float t2 = tx * tx + ty * ty + tz * tz;
        if (!(t2 > thr)) {
            // process region: exact reference math
            const ull ncx2 = pk2(-cx, -cx);
            const ull ncy2 = pk2(-cy, -cy);
            const ull ncz2 = pk2(-cz, -cz);
            float bestv = -1.0f;
#pragma unroll
            for (int i = 0; i < 4; i++) {
                ull dx2 = add2(px2[i], ncx2);
                ull dy2 = add2(py2[i], ncy2);
                ull dz2 = add2(pz2[i], ncz2);
                ull d2 = add2(add2(mul2(dx2, dx2), mul2(dy2, dy2)), mul2(dz2, dz2));
                float d0, d1;
                upk2(d0, d1, d2);
                float n0 = fminf(dist[2 * i], d0);
                float n1 = fminf(dist[2 * i + 1], d1);
                dist[2 * i] = n0;
                dist[2 * i + 1] = n1;
                bestv = fmaxf(bestv, fmaxf(n0, n1));
            }
            unsigned wm = __reduce_max_sync(FULLMASK, __float_as_uint(bestv));
            float wmf = __uint_as_float(wm);
            unsigned cand = 0xFFFFFFFFu;
#pragma unroll
            for (int sl = 0; sl < 8; sl++) {
                unsigned oi = (sl < 4)
                    ? (unsigned)((o2.x >> (16 * sl)) & 0xFFFFull)
                    : (unsigned)((o2.y >> (16 * (sl - 4))) & 0xFFFFull);
                if (dist[sl] == wmf && oi < cand) cand = oi;
            }
            cand = __reduce_min_sync(FULLMASK, cand);
            regval = wm;
            regidx = cand;
            float sq = gr + sqrtf(wmf);
            thr = sq * sq * 1.001f;
        }

        if (lane == 0) { s_val[s & 1][warp] = regval; s_idx[s & 1][warp] = regidx; }
        __syncthreads();

        // every warp redundantly reduces the 32 region partials
        unsigned v = s_val[s & 1][lane];
        unsigned ci = s_idx[s & 1][lane];
        unsigned gm = __reduce_max_sync(FULLMASK, v);
        unsigned c2 = (v == gm) ? ci : 0xFFFFFFFFu;
        int widx = (int)__reduce_min_sync(FULLMASK, c2);

        cx = X[widx * 3 + 0];
        cy = X[widx * 3 + 1];
        cz = X[widx * 3 + 2];
        if (t == 0) {
            float* o = g_newxyz + (size_t)(b * SS + s + 1) * 3;
            o[0] = cx; o[1] = cy; o[2] = cz;
        }
    }
}

// =====================================================================
// K2: kNN (K=32) + group stats. 512 threads/block (128-reg cap => no
// spills), 128 blocks, warp per query (8 queries/warp). Buffered bitonic
// top-32; key = (orderable(d) << 13) | idx; selected SET == lax.top_k.
// =====================================================================
__device__ __forceinline__ ull u64min(ull a, ull b) { return a < b ? a : b; }
__device__ __forceinline__ ull u64max(ull a, ull b) { return a < b ? b : a; }
__device__ __forceinline__ ull makekey(float d, int idx) {
    unsigned ub = __float_as_uint(d);
    ub ^= ((unsigned)((int)ub >> 31)) | 0x80000000u;
    return ((ull)ub << 13) | (unsigned)idx;
}
__device__ __forceinline__ float kth2kd(ull kth) {
    unsigned ub = (unsigned)(kth >> 13);
    unsigned db = (ub >> 31) ? (ub ^ 0x80000000u) : ~ub;
    return __uint_as_float(db);
}
__device__ __forceinline__ ull sort32(ull key, int lane)
{
#pragma unroll
    for (int k = 2; k <= 32; k <<= 1) {
#pragma unroll
        for (int j = k >> 1; j > 0; j >>= 1) {
            ull other = __shfl_xor_sync(FULLMASK, key, j);
            bool up = ((lane & k) == 0);
            bool takeMin = (((lane & j) == 0) == up);
            key = takeMin ? u64min(key, other) : u64max(key, other);
        }
    }
    return key;
}
__device__ __forceinline__ ull merge32(ull key, ull buf, int lane)
{
    buf = sort32(buf, lane);
    ull rev = __shfl_sync(FULLMASK, buf, 31 - lane);
    key = u64min(key, rev);
#pragma unroll
    for (int j = 16; j > 0; j >>= 1) {
        ull other = __shfl_xor_sync(FULLMASK, key, j);
        bool takeMin = ((lane & j) == 0);
        key = takeMin ? u64min(key, other) : u64max(key, other);
    }
    return key;
}
__device__ __forceinline__ void push_chunk(ull ck, unsigned m, int lane,
                                           ull& key, ull& kth, float& kd,
                                           ull& buf, int& bcnt)
{
    int cnt = __popc(m);
    int r = lane - bcnt;
    bool take = (r >= 0) && (r < cnt);
    unsigned pos = __fns(m, 0, take ? (r + 1) : 1);
    ull got = __shfl_sync(FULLMASK, ck, pos & 31);
    if (take) buf = got;
    bcnt += cnt;
    if (bcnt >= 32) {
        key = merge32(key, buf, lane);
        kth = __shfl_sync(FULLMASK, key, 31);
        kd = kth2kd(kth);
        int left = bcnt - 32;
        buf = ~0ull;
        if (left) {
            int start = cnt - left;
            bool tk2 = lane < left;
            unsigned pos2 = __fns(m, 0, tk2 ? (start + lane + 1) : 1);
            ull got2 = __shfl_sync(FULLMASK, ck, pos2 & 31);
            if (tk2) buf = got2;
        }
        bcnt = left;
    }
}

__global__ void __launch_bounds__(512) knn_kernel(const float* __restrict__ xyz)
{
    extern __shared__ float4 spts[];    // [NN] : x, y, z, |p|^2  (128KB)
    __shared__ double s_p1[16], s_p2[16];

    const int b  = blockIdx.x >> 3;     // 8 query-chunks (128 queries) per batch
    const int qc = blockIdx.x & 7;
    const float* X = xyz + (size_t)b * NN * 3;

    for (int p = threadIdx.x; p < NN; p += 512) {
        float x = X[p * 3], y = X[p * 3 + 1], z = X[p * 3 + 2];
        float sq = __fadd_rn(__fadd_rn(__fmul_rn(x, x), __fmul_rn(y, y)),
                             __fmul_rn(z, z));
        spts[p] = make_float4(x, y, z, sq);
    }
    __syncthreads();

    const int warp = threadIdx.x >> 5;
    const int lane = threadIdx.x & 31;
    const ull m2two = pk2(-2.0f, -2.0f);

    double acc1 = 0.0, acc2 = 0.0;      // meaningful on lane 0 only

    for (int qi = 0; qi < 8; qi++) {
        const int s = qc * 128 + warp * 8 + qi;
        const float* cen = g_newxyz + (size_t)(b * SS + s) * 3;
        const float cx = cen[0], cy = cen[1], cz = cen[2];
        const float csq = __fadd_rn(__fadd_rn(__fmul_rn(cx, cx), __fmul_rn(cy, cy)),
                                    __fmul_rn(cz, cz));
        const ull cX2 = pk2(cx, cx), cY2 = pk2(cy, cy), cZ2 = pk2(cz, cz);
        const ull csq2 = pk2(csq, csq);

        ull key;
        {
            float4 pt = spts[lane];
            float dot = __fadd_rn(__fadd_rn(__fmul_rn(pt.x, cx), __fmul_rn(pt.y, cy)),
                                  __fmul_rn(pt.z, cz));
            float d = __fadd_rn(__fadd_rn(__fmul_rn(-2.0f, dot), csq), pt.w);
            key = sort32(makekey(d, lane), lane);
            float4 p2 = spts[32 + lane];
            float dot2 = __fadd_rn(__fadd_rn(__fmul_rn(p2.x, cx), __fmul_rn(p2.y, cy)),
                                   __fmul_rn(p2.z, cz));
            float dB = __fadd_rn(__fadd_rn(__fmul_rn(-2.0f, dot2), csq), p2.w);
            key = merge32(key, makekey(dB, 32 + lane), lane);
        }
        ull kth = __shfl_sync(FULLMASK, key, 31);
        float kd = kth2kd(kth);
        ull buf = ~0ull;
        int bcnt = 0;

        int base = 64;
        for (; base + 128 <= NN; base += 128) {
            const int p0 = base + lane;
            float4 a  = spts[p0];
            float4 b4 = spts[p0 + 32];
            float4 c  = spts[p0 + 64];
            float4 e  = spts[p0 + 96];
            ull XA = pk2(a.x, b4.x), YA = pk2(a.y, b4.y);
            ull ZA = pk2(a.z, b4.z), WA = pk2(a.w, b4.w);
            ull XB = pk2(c.x, e.x),  YB = pk2(c.y, e.y);
            ull ZB = pk2(c.z, e.z),  WB = pk2(c.w, e.w);
            ull dotA = add2(add2(mul2(XA, cX2), mul2(YA, cY2)), mul2(ZA, cZ2));
            ull dotB = add2(add2(mul2(XB, cX2), mul2(YB, cY2)), mul2(ZB, cZ2));
            ull dA = add2(add2(mul2(m2two, dotA), csq2), WA);
            ull dB = add2(add2(mul2(m2two, dotB), csq2), WB);
            float d0, d1, d2, d3;
            upk2(d0, d1, dA);
            upk2(d2, d3, dB);
            bool hit = (d0 <= kd) | (d1 <= kd) | (d2 <= kd) | (d3 <= kd);
            if (__any_sync(FULLMASK, hit)) {
                unsigned m0 = __ballot_sync(FULLMASK, d0 <= kd);
                if (m0) push_chunk(makekey(d0, p0), m0, lane, key, kth, kd, buf, bcnt);
                unsigned m1 = __ballot_sync(FULLMASK, d1 <= kd);
                if (m1) push_chunk(makekey(d1, p0 + 32), m1, lane, key, kth, kd, buf, bcnt);
                unsigned m2 = __ballot_sync(FULLMASK, d2 <= kd);
                if (m2) push_chunk(makekey(d2, p0 + 64), m2, lane, key, kth, kd, buf, bcnt);
                unsigned m3 = __ballot_sync(FULLMASK, d3 <= kd);
                if (m3) push_chunk(makekey(d3, p0 + 96), m3, lane, key, kth, kd, buf, bcnt);
            }
        }
        for (; base < NN; base += 64) {
            const int p0 = base + lane;
            float4 a = spts[p0];
            float4 c = spts[p0 + 32];
            ull X2 = pk2(a.x, c.x), Y2 = pk2(a.y, c.y);
            ull Z2 = pk2(a.z, c.z), W2 = pk2(a.w, c.w);
            ull dot2 = add2(add2(mul2(X2, cX2), mul2(Y2, cY2)), mul2(Z2, cZ2));
            ull d2p = add2(add2(mul2(m2two, dot2), csq2), W2);
            float d0, d1;
            upk2(d0, d1, d2p);
            bool hit = (d0 <= kd) | (d1 <= kd);
            if (__any_sync(FULLMASK, hit)) {
                unsigned m0 = __ballot_sync(FULLMASK, d0 <= kd);
                if (m0) push_chunk(makekey(d0, p0), m0, lane, key, kth, kd, buf, bcnt);
                unsigned m1 = __ballot_sync(FULLMASK, d1 <= kd);
                if (m1) push_chunk(makekey(d1, p0 + 32), m1, lane, key, kth, kd, buf, bcnt);
            }
        }
        if (bcnt > 0) key = merge32(key, buf, lane);   // empty slots hold MAX

        // ----- group stats over the kept 32 neighbors -----
        int ki = (int)(key & 0x1FFFull);
        float4 q = spts[ki];
        float dx = __fsub_rn(q.x, cx);
        float dy = __fsub_rn(q.y, cy);
        float dz = __fsub_rn(q.z, cz);
        float sdx = dx, sdy = dy, sdz = dz;
        float mdx = dx, mdy = dy, mdz = dz;
        float s1 = dx + dy + dz;
        float s2 = dx * dx + dy * dy + dz * dz;
#pragma unroll
        for (int o = 16; o; o >>= 1) {
            sdx += __shfl_down_sync(FULLMASK, sdx, o);
            sdy += __shfl_down_sync(FULLMASK, sdy, o);
            sdz += __shfl_down_sync(FULLMASK, sdz, o);
            mdx = fmaxf(mdx, __shfl_down_sync(FULLMASK, mdx, o));
            mdy = fmaxf(mdy, __shfl_down_sync(FULLMASK, mdy, o));
            mdz = fmaxf(mdz, __shfl_down_sync(FULLMASK, mdz, o));
            s1 += __shfl_down_sync(FULLMASK, s1, o);
            s2 += __shfl_down_sync(FULLMASK, s2, o);
        }
        if (lane == 0) {
            int ix = (b * SS + s) * 3;
            g_gsum[ix] = sdx; g_gsum[ix + 1] = sdy; g_gsum[ix + 2] = sdz;
            g_gmax[ix] = mdx; g_gmax[ix + 1] = mdy; g_gmax[ix + 2] = mdz;
            acc1 += (double)s1;
            acc2 += (double)s2;
        }
    }

    if (lane == 0) { s_p1[warp] = acc1; s_p2[warp] = acc2; }
    __syncthreads();
    if (threadIdx.x == 0) {
        double a = 0.0, c = 0.0;
        for (int w = 0; w < 16; w++) { a += s_p1[w]; c += s_p2[w]; }
        atomicAdd(&g_acc[0], a);
        atomicAdd(&g_acc[1], c);
    }
}

// =====================================================================
// K3: std, lc, BN1+relu, safe_cdist, BN2+relu. Single block.
// =====================================================================
__global__ void __launch_bounds__(1024) finalize_kernel(
    const float* __restrict__ bn1g, const float* __restrict__ bn1b,
    const float* __restrict__ bn2g, const float* __restrict__ bn2b,
    float* __restrict__ out)
{
    const int t = threadIdx.x;
    const int lane = t & 31, warp = t >> 5;

    __shared__ float s_red[32];
    __shared__ float s_se;
    __shared__ float s_mean[6], s_var[6];
    __shared__ float s_tf[BB * 36];
    __shared__ float s_m2[36], s_v2[36];

    if (t == 0) {
        double M = (double)BB * SS * KK * 3;
        double var = (g_acc[1] - g_acc[0] * g_acc[0] / M) / (M - 1.0); // ddof=1
        s_se = (float)sqrt(var) + 1e-5f;
    }
    __syncthreads();
    const float se = s_se;

    for (int idx = t; idx < BB * SS; idx += 1024) {
        int b = idx >> 10, s = idx & (SS - 1);
        const float* gm = g_gmax + idx * 3;
        const float* gs = g_gsum + idx * 3;
        const float* cn = g_newxyz + idx * 3;
#pragma unroll
        for (int c = 0; c < 3; c++) {
            float mx = __fdiv_rn(gm[c], se);
            float mn = __fdiv_rn(__fdiv_rn(gs[c], 32.0f), se);
            g_lc[(b * 6 + c) * SS + s] = __fadd_rn(mx, mn);
        }
#pragma unroll
        for (int c = 0; c < 3; c++) {
            float v = cn[c];
            g_lc[(b * 6 + 3 + c) * SS + s] = v + v;
        }
    }
    __syncthreads();

    for (int c = 0; c < 6; c++) {
        float part = 0.0f;
        for (int i = t; i < BB * SS; i += 1024) {
            int b = i >> 10, s = i & 1023;
            part += g_lc[(b * 6 + c) * SS + s];
        }
#pragma unroll
        for (int o = 16; o; o >>= 1) part += __shfl_down_sync(FULLMASK, part, o);
        if (lane == 0) s_red[warp] = part;
        __syncthreads();
        if (t == 0) {
            float tot = 0.0f;
            for (int w = 0; w < 32; w++) tot += s_red[w];
            s_mean[c] = tot / (float)(BB * SS);
        }
        __syncthreads();
        float m = s_mean[c];
        part = 0.0f;
        for (int i = t; i < BB * SS; i += 1024) {
            int b = i >> 10, s = i & 1023;
            float d = g_lc[(b * 6 + c) * SS + s] - m;
            part += d * d;
        }
#pragma unroll
        for (int o = 16; o; o >>= 1) part += __shfl_down_sync(FULLMASK, part, o);
        if (lane == 0) s_red[warp] = part;
        __syncthreads();
        if (t == 0) {
            float tot = 0.0f;
            for (int w = 0; w < 32; w++) tot += s_red[w];
            s_var[c] = tot / (float)(BB * SS);   // biased, as in reference
        }
        __syncthreads();
    }
    for (int c = 0; c < 6; c++) {
        float m = s_mean[c], v = s_var[c];
        float g = bn1g[c], bt = bn1b[c];
        float den = sqrtf(v + 1e-5f);
        for (int i = t; i < BB * SS; i += 1024) {
            int b = i >> 10, s = i & 1023;
            int ix = (b * 6 + c) * SS + s;
            float y = (g_lc[ix] - m) / den * g + bt;
            g_lc[ix] = fmaxf(y, 0.0f);
        }
    }
    __syncthreads();

    if (t < BB * 6) {
        int b = t / 6, c = t % 6;
        s_tf[b * 36 + c * 6 + c] = 0.0f;
    }
    for (int task = warp; task < BB * 15; task += 32) {
        int b = task / 15, pr = task % 15;
        int i = 0, j = 0, p = pr;
        for (i = 0; i < 5; i++) {
            int row = 5 - i;
            if (p < row) { j = i + 1 + p; break; }
            p -= row;
        }
        const float* A  = g_lc + (b * 6 + i) * SS;
        const float* Bp = g_lc + (b * 6 + j) * SS;
        float part = 0.0f;
        for (int s = lane; s < SS; s += 32) {
            float d = A[s] - Bp[s];
            part += d * d;
        }
#pragma unroll
        for (int o = 16; o; o >>= 1) part += __shfl_down_sync(FULLMASK, part, o);
        if (lane == 0) {
            float v = part > 0.0f ? sqrtf(part) : 0.0f;
            s_tf[b * 36 + i * 6 + j] = v;
            s_tf[b * 36 + j * 6 + i] = v;
        }
    }
    __syncthreads();

    if (t < 36) {
        float m = 0.0f;
        for (int b = 0; b < BB; b++) m += s_tf[b * 36 + t];
        m /= (float)BB;
        float v = 0.0f;
        for (int b = 0; b < BB; b++) {
            float d = s_tf[b * 36 + t] - m;
            v += d * d;
        }
        v /= (float)BB;
        s_m2[t] = m; s_v2[t] = v;
    }
    __syncthreads();
    if (t < BB * 36) {
        int b = t / 36, f = t % 36;
        float x = s_tf[b * 36 + f];
        float y = (x - s_m2[f]) / sqrtf(s_v2[f] + 1e-5f) * bn2g[f] + bn2b[f];
        out[t] = fmaxf(y, 0.0f);
    }
}

// =====================================================================
extern "C" void kernel_launch(void* const* d_in, const int* in_sizes, int n_in,
                              void* d_out, int out_size)
{
    const float* xyz  = (const float*)d_in[0];
    const float* bn1g = (const float*)d_in[1];
    const float* bn1b = (const float*)d_in[2];
    const float* bn2g = (const float*)d_in[3];
    const float* bn2b = (const float*)d_in[4];
    float* out = (float*)d_out;

    // idempotent host-side attribute sets (capture-safe)
    cudaFuncSetAttribute(setup_kernel, cudaFuncAttributeMaxDynamicSharedMemorySize,
                         NN * (int)sizeof(ull));
    cudaFuncSetAttribute(knn_kernel, cudaFuncAttributeMaxDynamicSharedMemorySize,
                         NN * (int)sizeof(float4));

    setup_kernel<<<BB, 1024, NN * sizeof(ull)>>>(xyz);
    fps_kernel<<<BB, 1024>>>(xyz);
    knn_kernel<<<BB * 8, 512, NN * sizeof(float4)>>>(xyz);
    finalize_kernel<<<1, 1024>>>(bn1g, bn1b, bn2g, bn2b, out);
}

// round 8
// speedup vs baseline: 1.0520x; 1.0520x over previous
#include <cuda_runtime.h>
#include <cuda_bf16.h>

#define BB 16
#define NN 8192
#define SS 1024
#define KK 32
#define FULLMASK 0xFFFFFFFFu
typedef unsigned long long ull;

// ---------------- scratch (no allocs allowed) ----------------
__device__ float  g_newxyz[BB * SS * 3];   // FPS-selected centers
__device__ float  g_gmax[BB * SS * 3];     // max over K of diff, per coord
__device__ float  g_gsum[BB * SS * 3];     // sum over K of diff, per coord
__device__ double g_acc[2];                // sum(diff), sum(diff^2) for global std
__device__ float  g_lc[BB * 6 * SS];       // pooled features (raw, pre-BN1)
__device__ float  g_ppts[BB * NN * 3];     // Morton-permuted coords
__device__ unsigned short g_oidxT[BB * NN];// per-thread-transposed orig indices
__device__ float4 g_ctr[BB * 32];          // region centroid + padded radius

// ---------------- f32x2 helpers (Blackwell packed fp32) ----------------
__device__ __forceinline__ ull pk2(float lo, float hi) {
    ull r;
    asm("mov.b64 %0, {%1, %2};" : "=l"(r) : "f"(lo), "f"(hi));
    return r;
}
__device__ __forceinline__ void upk2(float& lo, float& hi, ull v) {
    asm("mov.b64 {%0, %1}, %2;" : "=f"(lo), "=f"(hi) : "l"(v));
}
__device__ __forceinline__ ull add2(ull a, ull b) {
    ull r;
    asm("add.rn.f32x2 %0, %1, %2;" : "=l"(r) : "l"(a), "l"(b));
    return r;
}
__device__ __forceinline__ ull mul2(ull a, ull b) {
    ull r;
    asm("mul.rn.f32x2 %0, %1, %2;" : "=l"(r) : "l"(a), "l"(b));
    return r;
}

// =====================================================================
// K0: setup — bbox, Morton codes, bitonic sort, permuted coords, region
// centroid+radius (padded). Order only affects FPS pruning efficiency,
// never correctness.
// =====================================================================
__device__ __forceinline__ unsigned expand10(unsigned v) {
    v &= 1023u;
    v = (v | (v << 16)) & 0x030000FFu;
    v = (v | (v << 8))  & 0x0300F00Fu;
    v = (v | (v << 4))  & 0x030C30C3u;
    v = (v | (v << 2))  & 0x09249249u;
    return v;
}

__global__ void __launch_bounds__(1024) setup_kernel(const float* __restrict__ xyz)
{
    extern __shared__ ull skeys[];              // [NN] 64KB
    __shared__ float s_bb[6][32];
    __shared__ float s_box[6];
    const int b = blockIdx.x, t = threadIdx.x;
    const int lane = t & 31, warp = t >> 5;
    const float* X = xyz + (size_t)b * NN * 3;

    float mnx = 1e30f, mny = 1e30f, mnz = 1e30f;
    float mxx = -1e30f, mxy = -1e30f, mxz = -1e30f;
    float xs[8], ys[8], zs[8];
#pragma unroll
    for (int i = 0; i < 8; i++) {
        int p = t + (i << 10);
        float x = X[p * 3], y = X[p * 3 + 1], z = X[p * 3 + 2];
        xs[i] = x; ys[i] = y; zs[i] = z;
        mnx = fminf(mnx, x); mxx = fmaxf(mxx, x);
        mny = fminf(mny, y); mxy = fmaxf(mxy, y);
        mnz = fminf(mnz, z); mxz = fmaxf(mxz, z);
    }
#pragma unroll
    for (int o = 16; o; o >>= 1) {
        mnx = fminf(mnx, __shfl_xor_sync(FULLMASK, mnx, o));
        mny = fminf(mny, __shfl_xor_sync(FULLMASK, mny, o));
        mnz = fminf(mnz, __shfl_xor_sync(FULLMASK, mnz, o));
        mxx = fmaxf(mxx, __shfl_xor_sync(FULLMASK, mxx, o));
        mxy = fmaxf(mxy, __shfl_xor_sync(FULLMASK, mxy, o));
        mxz = fmaxf(mxz, __shfl_xor_sync(FULLMASK, mxz, o));
    }
    if (lane == 0) {
        s_bb[0][warp] = mnx; s_bb[1][warp] = mny; s_bb[2][warp] = mnz;
        s_bb[3][warp] = mxx; s_bb[4][warp] = mxy; s_bb[5][warp] = mxz;
    }
    __syncthreads();
    if (warp == 0) {
        float v0 = s_bb[0][lane], v1 = s_bb[1][lane], v2 = s_bb[2][lane];
        float v3 = s_bb[3][lane], v4 = s_bb[4][lane], v5 = s_bb[5][lane];
#pragma unroll
        for (int o = 16; o; o >>= 1) {
            v0 = fminf(v0, __shfl_xor_sync(FULLMASK, v0, o));
            v1 = fminf(v1, __shfl_xor_sync(FULLMASK, v1, o));
            v2 = fminf(v2, __shfl_xor_sync(FULLMASK, v2, o));
            v3 = fmaxf(v3, __shfl_xor_sync(FULLMASK, v3, o));
            v4 = fmaxf(v4, __shfl_xor_sync(FULLMASK, v4, o));
            v5 = fmaxf(v5, __shfl_xor_sync(FULLMASK, v5, o));
        }
        if (lane == 0) {
            s_box[0] = v0; s_box[1] = v1; s_box[2] = v2;
            s_box[3] = v3; s_box[4] = v4; s_box[5] = v5;
        }
    }
    __syncthreads();
    const float bx = s_box[0], by = s_box[1], bz = s_box[2];
    const float fx = 1023.0f / fmaxf(s_box[3] - bx, 1e-20f);
    const float fy = 1023.0f / fmaxf(s_box[4] - by, 1e-20f);
    const float fz = 1023.0f / fmaxf(s_box[5] - bz, 1e-20f);

#pragma unroll
    for (int i = 0; i < 8; i++) {
        int p = t + (i << 10);
        unsigned qx = (unsigned)fminf(fmaxf((xs[i] - bx) * fx, 0.f), 1023.f);
        unsigned qy = (unsigned)fminf(fmaxf((ys[i] - by) * fy, 0.f), 1023.f);
        unsigned qz = (unsigned)fminf(fmaxf((zs[i] - bz) * fz, 0.f), 1023.f);
        unsigned code = expand10(qx) | (expand10(qy) << 1) | (expand10(qz) << 2);
        skeys[p] = ((ull)code << 13) | (unsigned)p;
    }
    __syncthreads();

    // bitonic sort ascending, 4096 pairs / 1024 threads per stage
    for (int k = 2; k <= NN; k <<= 1) {
        for (int j = k >> 1; j > 0; j >>= 1) {
#pragma unroll
            for (int m = 0; m < 4; m++) {
                int pi = t + (m << 10);
                int i0 = ((pi & ~(j - 1)) << 1) | (pi & (j - 1));
                int i1 = i0 | j;
                ull a = skeys[i0], c = skeys[i1];
                bool up = ((i0 & k) == 0);
                if ((a > c) == up) { skeys[i0] = c; skeys[i1] = a; }
            }
            __syncthreads();
        }
    }

    // permuted outputs + per-warp region stats (region = 256 consecutive)
    float px[8], py[8], pz[8];
    float sx = 0.f, sy = 0.f, sz = 0.f;
#pragma unroll
    for (int i = 0; i < 8; i++) {
        int j = warp * 256 + i * 32 + lane;
        int o = (int)(skeys[j] & 0x1FFFull);
        float x = X[o * 3], y = X[o * 3 + 1], z = X[o * 3 + 2];
        px[i] = x; py[i] = y; pz[i] = z;
        float* dst = g_ppts + ((size_t)b * NN + j) * 3;
        dst[0] = x; dst[1] = y; dst[2] = z;
        g_oidxT[((size_t)b * 1024 + t) * 8 + i] = (unsigned short)o;
        sx += x; sy += y; sz += z;
    }
#pragma unroll
    for (int o = 16; o; o >>= 1) {
        sx += __shfl_xor_sync(FULLMASK, sx, o);
        sy += __shfl_xor_sync(FULLMASK, sy, o);
        sz += __shfl_xor_sync(FULLMASK, sz, o);
    }
    float cxm = sx * (1.0f / 256.0f), cym = sy * (1.0f / 256.0f), czm = sz * (1.0f / 256.0f);
    float md2 = 0.f;
#pragma unroll
    for (int i = 0; i < 8; i++) {
        float dx = px[i] - cxm, dy = py[i] - cym, dz = pz[i] - czm;
        md2 = fmaxf(md2, dx * dx + dy * dy + dz * dz);
    }
#pragma unroll
    for (int o = 16; o; o >>= 1)
        md2 = fmaxf(md2, __shfl_xor_sync(FULLMASK, md2, o));
    if (lane == 0) {
        float r = sqrtf(md2) * 1.001f + 1e-6f;   // padded radius
        g_ctr[b * 32 + warp] = make_float4(cxm, cym, czm, r);
    }
}

// =====================================================================
// K1: FPS with region pruning (proven exact in R7). 16 blocks x 1024
// threads; warp owns 256 Morton-consecutive points. Skipped updates are
// provably no-ops; cached (max, min-orig-idx) per region stays exact.
// =====================================================================
__global__ void __launch_bounds__(1024) fps_kernel(const float* __restrict__ xyz)
{
    const int b = blockIdx.x;
    const int t = threadIdx.x;
    const int lane = t & 31, warp = t >> 5;
    const float* X = xyz + (size_t)b * NN * 3;
    const float* P = g_ppts + (size_t)b * NN * 3;

    ull px2[4], py2[4], pz2[4];
    float dist[8];
    const int base = warp * 256 + lane;
#pragma unroll
    for (int i = 0; i < 4; i++) {
        int p0 = base + (2 * i) * 32;
        int p1 = base + (2 * i + 1) * 32;
        px2[i] = pk2(P[p0 * 3 + 0], P[p1 * 3 + 0]);
        py2[i] = pk2(P[p0 * 3 + 1], P[p1 * 3 + 1]);
        pz2[i] = pk2(P[p0 * 3 + 2], P[p1 * 3 + 2]);
        dist[2 * i] = 1e10f;
        dist[2 * i + 1] = 1e10f;
    }
    const ulonglong2 o2 = *reinterpret_cast<const ulonglong2*>(
        g_oidxT + ((size_t)b * 1024 + t) * 8);
    const float4 cr = g_ctr[b * 32 + warp];
    const float gx = cr.x, gy = cr.y, gz = cr.z, gr = cr.w;

    unsigned regval = __float_as_uint(1e10f);
    unsigned regidx = 0;
    float    thr    = 3.0e38f;

    __shared__ unsigned s_val[2][32];
    __shared__ unsigned s_idx[2][32];

    if (t == 0 && b == 0) { g_acc[0] = 0.0; g_acc[1] = 0.0; }  // reset per replay
    float cx = X[0], cy = X[1], cz = X[2];     // sample 0 = point 0
    if (t == 0) {
        float* o = g_newxyz + (size_t)(b * SS) * 3;
        o[0] = cx; o[1] = cy; o[2] = cz;
    }

    for (int s = 0; s < SS - 1; s++) {
        float tx = cx - gx, ty = cy - gy, tz = cz - gz;
        float t2 = tx * tx + ty * ty + tz * tz;
        if (!(t2 > thr)) {
            const ull ncx2 = pk2(-cx, -cx);
            const ull ncy2 = pk2(-cy, -cy);
            const ull ncz2 = pk2(-cz, -cz);
            float bestv = -1.0f;
#pragma unroll
            for (int i = 0; i < 4; i++) {
                ull dx2 = add2(px2[i], ncx2);
                ull dy2 = add2(py2[i], ncy2);
                ull dz2 = add2(pz2[i], ncz2);
                ull d2 = add2(add2(mul2(dx2, dx2), mul2(dy2, dy2)), mul2(dz2, dz2));
                float d0, d1;
                upk2(d0, d1, d2);
                float n0 = fminf(dist[2 * i], d0);
                float n1 = fminf(dist[2 * i + 1], d1);
                dist[2 * i] = n0;
                dist[2 * i + 1] = n1;
                bestv = fmaxf(bestv, fmaxf(n0, n1));
            }
            unsigned wm = __reduce_max_sync(FULLMASK, __float_as_uint(bestv));
            float wmf = __uint_as_float(wm);
            unsigned cand = 0xFFFFFFFFu;
#pragma unroll
            for (int sl = 0; sl < 8; sl++) {
                unsigned oi = (sl < 4)
                    ? (unsigned)((o2.x >> (16 * sl)) & 0xFFFFull)
                    : (unsigned)((o2.y >> (16 * (sl - 4))) & 0xFFFFull);
                if (dist[sl] == wmf && oi < cand) cand = oi;
            }
            cand = __reduce_min_sync(FULLMASK, cand);
            regval = wm;
            regidx = cand;
            float sq = gr + sqrtf(wmf);
            thr = sq * sq * 1.001f;
        }

        if (lane == 0) { s_val[s & 1][warp] = regval; s_idx[s & 1][warp] = regidx; }
        __syncthreads();

        unsigned v = s_val[s & 1][lane];
        unsigned ci = s_idx[s & 1][lane];
        unsigned gm = __reduce_max_sync(FULLMASK, v);
        unsigned c2 = (v == gm) ? ci : 0xFFFFFFFFu;
        int widx = (int)__reduce_min_sync(FULLMASK, c2);

        cx = X[widx * 3 + 0];
        cy = X[widx * 3 + 1];
        cz = X[widx * 3 + 2];
        if (t == 0) {
            float* o = g_newxyz + (size_t)(b * SS + s + 1) * 3;
            o[0] = cx; o[1] = cy; o[2] = cz;
        }
    }
}

// =====================================================================
// K2: kNN (K=32) + group stats — R4 config: 128 blocks x 1024 threads
// (32 warps/SM), warp per query, 4 queries/warp. Buffered bitonic top-32.
// =====================================================================
__device__ __forceinline__ ull u64min(ull a, ull b) { return a < b ? a : b; }
__device__ __forceinline__ ull u64max(ull a, ull b) { return a < b ? b : a; }
__device__ __forceinline__ ull makekey(float d, int idx) {
    unsigned ub = __float_as_uint(d);
    ub ^= ((unsigned)((int)ub >> 31)) | 0x80000000u;
    return ((ull)ub << 13) | (unsigned)idx;
}
__device__ __forceinline__ float kth2kd(ull kth) {
    unsigned ub = (unsigned)(kth >> 13);
    unsigned db = (ub >> 31) ? (ub ^ 0x80000000u) : ~ub;
    return __uint_as_float(db);
}
__device__ __forceinline__ ull sort32(ull key, int lane)
{
#pragma unroll
    for (int k = 2; k <= 32; k <<= 1) {
#pragma unroll
        for (int j = k >> 1; j > 0; j >>= 1) {
            ull other = __shfl_xor_sync(FULLMASK, key, j);
            bool up = ((lane & k) == 0);
            bool takeMin = (((lane & j) == 0) == up);
            key = takeMin ? u64min(key, other) : u64max(key, other);
        }
    }
    return key;
}
__device__ __forceinline__ ull merge32(ull key, ull buf, int lane)
{
    buf = sort32(buf, lane);
    ull rev = __shfl_sync(FULLMASK, buf, 31 - lane);
    key = u64min(key, rev);
#pragma unroll
    for (int j = 16; j > 0; j >>= 1) {
        ull other = __shfl_xor_sync(FULLMASK, key, j);
        bool takeMin = ((lane & j) == 0);
        key = takeMin ? u64min(key, other) : u64max(key, other);
    }
    return key;
}
__device__ __forceinline__ void push_chunk(ull ck, unsigned m, int lane,
                                           ull& key, ull& kth, float& kd,
                                           ull& buf, int& bcnt)
{
    int cnt = __popc(m);
    int r = lane - bcnt;
    bool take = (r >= 0) && (r < cnt);
    unsigned pos = __fns(m, 0, take ? (r + 1) : 1);
    ull got = __shfl_sync(FULLMASK, ck, pos & 31);
    if (take) buf = got;
    bcnt += cnt;
    if (bcnt >= 32) {
        key = merge32(key, buf, lane);
        kth = __shfl_sync(FULLMASK, key, 31);
        kd = kth2kd(kth);
        int left = bcnt - 32;
        buf = ~0ull;
        if (left) {
            int start = cnt - left;
            bool tk2 = lane < left;
            unsigned pos2 = __fns(m, 0, tk2 ? (start + lane + 1) : 1);
            ull got2 = __shfl_sync(FULLMASK, ck, pos2 & 31);
            if (tk2) buf = got2;
        }
        bcnt = left;
    }
}

__global__ void __launch_bounds__(1024) knn_kernel(const float* __restrict__ xyz)
{
    extern __shared__ float4 spts[];    // [NN] : x, y, z, |p|^2  (128KB)
    __shared__ double s_p1[32], s_p2[32];

    const int b  = blockIdx.x >> 3;     // 8 query-chunks (128 queries) per batch
    const int qc = blockIdx.x & 7;
    const float* X = xyz + (size_t)b * NN * 3;

    for (int p = threadIdx.x; p < NN; p += 1024) {
        float x = X[p * 3], y = X[p * 3 + 1], z = X[p * 3 + 2];
        float sq = __fadd_rn(__fadd_rn(__fmul_rn(x, x), __fmul_rn(y, y)),
                             __fmul_rn(z, z));
        spts[p] = make_float4(x, y, z, sq);
    }
    __syncthreads();

    const int warp = threadIdx.x >> 5;
    const int lane = threadIdx.x & 31;
    const ull m2two = pk2(-2.0f, -2.0f);

    double acc1 = 0.0, acc2 = 0.0;      // meaningful on lane 0 only

    for (int qi = 0; qi < 4; qi++) {
        const int s = qc * 128 + warp * 4 + qi;
        const float* cen = g_newxyz + (size_t)(b * SS + s) * 3;
        const float cx = cen[0], cy = cen[1], cz = cen[2];
        const float csq = __fadd_rn(__fadd_rn(__fmul_rn(cx, cx), __fmul_rn(cy, cy)),
                                    __fmul_rn(cz, cz));
        const ull cX2 = pk2(cx, cx), cY2 = pk2(cy, cy), cZ2 = pk2(cz, cz);
        const ull csq2 = pk2(csq, csq);

        ull key;
        {
            float4 pt = spts[lane];
            float dot = __fadd_rn(__fadd_rn(__fmul_rn(pt.x, cx), __fmul_rn(pt.y, cy)),
                                  __fmul_rn(pt.z, cz));
            float d = __fadd_rn(__fadd_rn(__fmul_rn(-2.0f, dot), csq), pt.w);
            key = sort32(makekey(d, lane), lane);
            float4 p2 = spts[32 + lane];
            float dot2 = __fadd_rn(__fadd_rn(__fmul_rn(p2.x, cx), __fmul_rn(p2.y, cy)),
                                   __fmul_rn(p2.z, cz));
            float dB = __fadd_rn(__fadd_rn(__fmul_rn(-2.0f, dot2), csq), p2.w);
            key = merge32(key, makekey(dB, 32 + lane), lane);
        }
        ull kth = __shfl_sync(FULLMASK, key, 31);
        float kd = kth2kd(kth);
        ull buf = ~0ull;
        int bcnt = 0;

        int base = 64;
        for (; base + 128 <= NN; base += 128) {
            const int p0 = base + lane;
            float4 a  = spts[p0];
            float4 b4 = spts[p0 + 32];
            float4 c  = spts[p0 + 64];
            float4 e  = spts[p0 + 96];
            ull XA = pk2(a.x, b4.x), YA = pk2(a.y, b4.y);
            ull ZA = pk2(a.z, b4.z), WA = pk2(a.w, b4.w);
            ull XB = pk2(c.x, e.x),  YB = pk2(c.y, e.y);
            ull ZB = pk2(c.z, e.z),  WB = pk2(c.w, e.w);
            ull dotA = add2(add2(mul2(XA, cX2), mul2(YA, cY2)), mul2(ZA, cZ2));
            ull dotB = add2(add2(mul2(XB, cX2), mul2(YB, cY2)), mul2(ZB, cZ2));
            ull dA = add2(add2(mul2(m2two, dotA), csq2), WA);
            ull dB = add2(add2(mul2(m2two, dotB), csq2), WB);
            float d0, d1, d2, d3;
            upk2(d0, d1, dA);
            upk2(d2, d3, dB);
            bool hit = (d0 <= kd) | (d1 <= kd) | (d2 <= kd) | (d3 <= kd);
            if (__any_sync(FULLMASK, hit)) {
                unsigned m0 = __ballot_sync(FULLMASK, d0 <= kd);
                if (m0) push_chunk(makekey(d0, p0), m0, lane, key, kth, kd, buf, bcnt);
                unsigned m1 = __ballot_sync(FULLMASK, d1 <= kd);
                if (m1) push_chunk(makekey(d1, p0 + 32), m1, lane, key, kth, kd, buf, bcnt);
                unsigned m2 = __ballot_sync(FULLMASK, d2 <= kd);
                if (m2) push_chunk(makekey(d2, p0 + 64), m2, lane, key, kth, kd, buf, bcnt);
                unsigned m3 = __ballot_sync(FULLMASK, d3 <= kd);
                if (m3) push_chunk(makekey(d3, p0 + 96), m3, lane, key, kth, kd, buf, bcnt);
            }
        }
        for (; base < NN; base += 64) {
            const int p0 = base + lane;
            float4 a = spts[p0];
            float4 c = spts[p0 + 32];
            ull X2 = pk2(a.x, c.x), Y2 = pk2(a.y, c.y);
            ull Z2 = pk2(a.z, c.z), W2 = pk2(a.w, c.w);
            ull dot2 = add2(add2(mul2(X2, cX2), mul2(Y2, cY2)), mul2(Z2, cZ2));
            ull d2p = add2(add2(mul2(m2two, dot2), csq2), W2);
            float d0, d1;
            upk2(d0, d1, d2p);
            bool hit = (d0 <= kd) | (d1 <= kd);
            if (__any_sync(FULLMASK, hit)) {
                unsigned m0 = __ballot_sync(FULLMASK, d0 <= kd);
                if (m0) push_chunk(makekey(d0, p0), m0, lane, key, kth, kd, buf, bcnt);
                unsigned m1 = __ballot_sync(FULLMASK, d1 <= kd);
                if (m1) push_chunk(makekey(d1, p0 + 32), m1, lane, key, kth, kd, buf, bcnt);
            }
        }
        if (bcnt > 0) key = merge32(key, buf, lane);   // empty slots hold MAX

        // ----- group stats over the kept 32 neighbors -----
        int ki = (int)(key & 0x1FFFull);
        float4 q = spts[ki];
        float dx = __fsub_rn(q.x, cx);
        float dy = __fsub_rn(q.y, cy);
        float dz = __fsub_rn(q.z, cz);
        float sdx = dx, sdy = dy, sdz = dz;
        float mdx = dx, mdy = dy, mdz = dz;
        float s1 = dx + dy + dz;
        float s2 = dx * dx + dy * dy + dz * dz;
#pragma unroll
        for (int o = 16; o; o >>= 1) {
            sdx += __shfl_down_sync(FULLMASK, sdx, o);
            sdy += __shfl_down_sync(FULLMASK, sdy, o);
            sdz += __shfl_down_sync(FULLMASK, sdz, o);
            mdx = fmaxf(mdx, __shfl_down_sync(FULLMASK, mdx, o));
            mdy = fmaxf(mdy, __shfl_down_sync(FULLMASK, mdy, o));
            mdz = fmaxf(mdz, __shfl_down_sync(FULLMASK, mdz, o));
            s1 += __shfl_down_sync(FULLMASK, s1, o);
            s2 += __shfl_down_sync(FULLMASK, s2, o);
        }
        if (lane == 0) {
            int ix = (b * SS + s) * 3;
            g_gsum[ix] = sdx; g_gsum[ix + 1] = sdy; g_gsum[ix + 2] = sdz;
            g_gmax[ix] = mdx; g_gmax[ix + 1] = mdy; g_gmax[ix + 2] = mdz;
            acc1 += (double)s1;
            acc2 += (double)s2;
        }
    }

    if (lane == 0) { s_p1[warp] = acc1; s_p2[warp] = acc2; }
    __syncthreads();
    if (threadIdx.x == 0) {
        double a = 0.0, c = 0.0;
        for (int w = 0; w < 32; w++) { a += s_p1[w]; c += s_p2[w]; }
        atomicAdd(&g_acc[0], a);
        atomicAdd(&g_acc[1], c);
    }
}

// =====================================================================
// K3a: lc build — 64 blocks x 256 threads (parallel, was serial in K3).
// =====================================================================
__global__ void __launch_bounds__(256) finalize1_kernel()
{
    const int idx = blockIdx.x * 256 + threadIdx.x;   // 0..16383
    // std (ddof=1) from global accumulators; redundant per-thread (cheap)
    double M = (double)BB * SS * KK * 3;
    double var = (g_acc[1] - g_acc[0] * g_acc[0] / M) / (M - 1.0);
    const float se = (float)sqrt(var) + 1e-5f;

    int b = idx >> 10, s = idx & (SS - 1);
    const float* gm = g_gmax + idx * 3;
    const float* gs = g_gsum + idx * 3;
    const float* cn = g_newxyz + idx * 3;
#pragma unroll
    for (int c = 0; c < 3; c++) {
        float mx = __fdiv_rn(gm[c], se);
        float mn = __fdiv_rn(__fdiv_rn(gs[c], 32.0f), se);
        g_lc[(b * 6 + c) * SS + s] = __fadd_rn(mx, mn);
    }
#pragma unroll
    for (int c = 0; c < 3; c++) {
        float v = cn[c];
        g_lc[(b * 6 + 3 + c) * SS + s] = v + v;
    }
}

// =====================================================================
// K3b: BN1 stats (fused 6-channel passes), cdist with on-the-fly
// normalize+relu, BN2. Single block.
// =====================================================================
__global__ void __launch_bounds__(1024) finalize2_kernel(
    const float* __restrict__ bn1g, const float* __restrict__ bn1b,
    const float* __restrict__ bn2g, const float* __restrict__ bn2b,
    float* __restrict__ out)
{
    const int t = threadIdx.x;
    const int lane = t & 31, warp = t >> 5;

    __shared__ float s_part[6][32];
    __shared__ float s_mean[6], s_den[6], s_g[6], s_bt[6];
    __shared__ float s_tf[BB * 36];
    __shared__ float s_m2[36], s_v2[36];

    // pass A: all 6 channel sums in one sweep
    float sum[6] = {0, 0, 0, 0, 0, 0};
    for (int i = t; i < BB * SS; i += 1024) {
        int b = i >> 10, s = i & 1023;
        const float* base = g_lc + (b * 6) * SS + s;
#pragma unroll
        for (int c = 0; c < 6; c++) sum[c] += base[c * SS];
    }
#pragma unroll
    for (int c = 0; c < 6; c++) {
#pragma unroll
        for (int o = 16; o; o >>= 1) sum[c] += __shfl_down_sync(FULLMASK, sum[c], o);
        if (lane == 0) s_part[c][warp] = sum[c];
    }
    __syncthreads();
    if (t < 6) {
        float tot = 0.0f;
        for (int w = 0; w < 32; w++) tot += s_part[t][w];
        s_mean[t] = tot / (float)(BB * SS);
        s_g[t] = bn1g[t];
        s_bt[t] = bn1b[t];
    }
    __syncthreads();

    // pass B: all 6 channel vars in one sweep
    float m0 = s_mean[0], m1 = s_mean[1], m2 = s_mean[2];
    float m3 = s_mean[3], m4 = s_mean[4], m5 = s_mean[5];
    float vs[6] = {0, 0, 0, 0, 0, 0};
    for (int i = t; i < BB * SS; i += 1024) {
        int b = i >> 10, s = i & 1023;
        const float* base = g_lc + (b * 6) * SS + s;
        float d0 = base[0 * SS] - m0; vs[0] += d0 * d0;
        float d1 = base[1 * SS] - m1; vs[1] += d1 * d1;
        float d2 = base[2 * SS] - m2; vs[2] += d2 * d2;
        float d3 = base[3 * SS] - m3; vs[3] += d3 * d3;
        float d4 = base[4 * SS] - m4; vs[4] += d4 * d4;
        float d5 = base[5 * SS] - m5; vs[5] += d5 * d5;
    }
#pragma unroll
    for (int c = 0; c < 6; c++) {
#pragma unroll
        for (int o = 16; o; o >>= 1) vs[c] += __shfl_down_sync(FULLMASK, vs[c], o);
        if (lane == 0) s_part[c][warp] = vs[c];
    }
    __syncthreads();
    if (t < 6) {
        float tot = 0.0f;
        for (int w = 0; w < 32; w++) tot += s_part[t][w];
        float var = tot / (float)(BB * SS);    // biased, as in reference
        s_den[t] = sqrtf(var + 1e-5f);
    }
    if (t < BB * 6) {
        int b = t / 6, c = t % 6;
        s_tf[b * 36 + c * 6 + c] = 0.0f;
    }
    __syncthreads();

    // cdist with on-the-fly BN1 normalize + relu
    for (int task = warp; task < BB * 15; task += 32) {
        int b = task / 15, pr = task % 15;
        int i = 0, j = 0, p = pr;
        for (i = 0; i < 5; i++) {
            int row = 5 - i;
            if (p < row) { j = i + 1 + p; break; }
            p -= row;
        }
        const float* A  = g_lc + (b * 6 + i) * SS;
        const float* Bp = g_lc + (b * 6 + j) * SS;
        float mi = s_mean[i], di = s_den[i], gi = s_g[i], bi = s_bt[i];
        float mj = s_mean[j], dj = s_den[j], gj = s_g[j], bj = s_bt[j];
        float part = 0.0f;
        for (int s = lane; s < SS; s += 32) {
            float a = fmaxf((A[s] - mi) / di * gi + bi, 0.0f);
            float c = fmaxf((Bp[s] - mj) / dj * gj + bj, 0.0f);
            float d = a - c;
            part += d * d;
        }
#pragma unroll
        for (int o = 16; o; o >>= 1) part += __shfl_down_sync(FULLMASK, part, o);
        if (lane == 0) {
            float v = part > 0.0f ? sqrtf(part) : 0.0f;   // zero-safe
            s_tf[b * 36 + i * 6 + j] = v;
            s_tf[b * 36 + j * 6 + i] = v;
        }
    }
    __syncthreads();

    // BN2 over batch (16) per feature (36)
    if (t < 36) {
        float m = 0.0f;
        for (int b = 0; b < BB; b++) m += s_tf[b * 36 + t];
        m /= (float)BB;
        float v = 0.0f;
        for (int b = 0; b < BB; b++) {
            float d = s_tf[b * 36 + t] - m;
            v += d * d;
        }
        v /= (float)BB;
        s_m2[t] = m; s_v2[t] = v;
    }
    __syncthreads();
    if (t < BB * 36) {
        int b = t / 36, f = t % 36;
        float x = s_tf[b * 36 + f];
        float y = (x - s_m2[f]) / sqrtf(s_v2[f] + 1e-5f) * bn2g[f] + bn2b[f];
        out[t] = fmaxf(y, 0.0f);
    }
}

// =====================================================================
extern "C" void kernel_launch(void* const* d_in, const int* in_sizes, int n_in,
                              void* d_out, int out_size)
{
    const float* xyz  = (const float*)d_in[0];
    const float* bn1g = (const float*)d_in[1];
    const float* bn1b = (const float*)d_in[2];
    const float* bn2g = (const float*)d_in[3];
    const float* bn2b = (const float*)d_in[4];
    float* out = (float*)d_out;

    // idempotent host-side attribute sets (capture-safe)
    cudaFuncSetAttribute(setup_kernel, cudaFuncAttributeMaxDynamicSharedMemorySize,
                         NN * (int)sizeof(ull));
    cudaFuncSetAttribute(knn_kernel, cudaFuncAttributeMaxDynamicSharedMemorySize,
                         NN * (int)sizeof(float4));

    setup_kernel<<<BB, 1024, NN * sizeof(ull)>>>(xyz);
    fps_kernel<<<BB, 1024>>>(xyz);
    knn_kernel<<<BB * 8, 1024, NN * sizeof(float4)>>>(xyz);
    finalize1_kernel<<<64, 256>>>();
    finalize2_kernel<<<1, 1024>>>(bn1g, bn1b, bn2g, bn2b, out);
}

// round 9
// speedup vs baseline: 1.3447x; 1.2783x over previous
#include <cuda_runtime.h>
#include <cuda_bf16.h>

#define BB 16
#define NN 8192
#define SS 1024
#define KK 32
#define FULLMASK 0xFFFFFFFFu
typedef unsigned long long ull;

// ---------------- scratch (no allocs allowed) ----------------
__device__ float  g_newxyz[BB * SS * 3];   // FPS-selected centers
__device__ float  g_gmax[BB * SS * 3];     // max over K of diff, per coord
__device__ float  g_gsum[BB * SS * 3];     // sum over K of diff, per coord
__device__ double g_acc[2];                // sum(diff), sum(diff^2) for global std
__device__ float  g_lc[BB * 6 * SS];       // pooled features (raw, pre-BN1)

// ---------------- f32x2 helpers (Blackwell packed fp32) ----------------
__device__ __forceinline__ ull pk2(float lo, float hi) {
    ull r;
    asm("mov.b64 %0, {%1, %2};" : "=l"(r) : "f"(lo), "f"(hi));
    return r;
}
__device__ __forceinline__ void upk2(float& lo, float& hi, ull v) {
    asm("mov.b64 {%0, %1}, %2;" : "=f"(lo), "=f"(hi) : "l"(v));
}
__device__ __forceinline__ ull add2(ull a, ull b) {
    ull r;
    asm("add.rn.f32x2 %0, %1, %2;" : "=l"(r) : "l"(a), "l"(b));
    return r;
}
__device__ __forceinline__ ull mul2(ull a, ull b) {
    ull r;
    asm("mul.rn.f32x2 %0, %1, %2;" : "=l"(r) : "l"(a), "l"(b));
    return r;
}

// =====================================================================
// K1: FPS (R4 version — best measured). 16 blocks x 1024 threads, 8
// pts/thread in registers, packed f32x2 math (bitwise identical to
// scalar rn ops): d = ((dx*dx + dy*dy) + dz*dz), dx = px + (-cx);
// distance = min(distance, d); argmax, lowest-index tie-break.
// REDUX warp reduces, ONE barrier/step, centroid via L1-resident LDG.
// =====================================================================
__global__ void __launch_bounds__(1024) fps_kernel(const float* __restrict__ xyz)
{
    const int b = blockIdx.x;
    const int t = threadIdx.x;
    const int lane = t & 31, warp = t >> 5;
    const float* X = xyz + (size_t)b * NN * 3;

    ull px2[4], py2[4], pz2[4];
    float dist[8];
#pragma unroll
    for (int i = 0; i < 4; i++) {
        int p0 = t + 1024 * (2 * i);
        int p1 = t + 1024 * (2 * i + 1);
        px2[i] = pk2(X[p0 * 3 + 0], X[p1 * 3 + 0]);
        py2[i] = pk2(X[p0 * 3 + 1], X[p1 * 3 + 1]);
        pz2[i] = pk2(X[p0 * 3 + 2], X[p1 * 3 + 2]);
        dist[2 * i] = 1e10f;
        dist[2 * i + 1] = 1e10f;
    }

    __shared__ unsigned s_val[2][32];
    __shared__ int      s_idx[2][32];

    if (t == 0 && b == 0) { g_acc[0] = 0.0; g_acc[1] = 0.0; }  // reset per replay
    float cx = X[0], cy = X[1], cz = X[2];   // sample 0 = point 0
    if (t == 0) {
        float* o = g_newxyz + (size_t)(b * SS) * 3;
        o[0] = cx; o[1] = cy; o[2] = cz;
    }

    for (int s = 0; s < SS - 1; s++) {
        const ull ncx2 = pk2(-cx, -cx);
        const ull ncy2 = pk2(-cy, -cy);
        const ull ncz2 = pk2(-cz, -cz);

        float bestv = -1.0f;
#pragma unroll
        for (int i = 0; i < 4; i++) {
            ull dx2 = add2(px2[i], ncx2);
            ull dy2 = add2(py2[i], ncy2);
            ull dz2 = add2(pz2[i], ncz2);
            ull d2 = add2(add2(mul2(dx2, dx2), mul2(dy2, dy2)), mul2(dz2, dz2));
            float d0, d1;
            upk2(d0, d1, d2);
            float n0 = fminf(dist[2 * i], d0);
            float n1 = fminf(dist[2 * i + 1], d1);
            dist[2 * i] = n0;
            dist[2 * i + 1] = n1;
            bestv = fmaxf(bestv, fmaxf(n0, n1));
        }

        unsigned wm = __reduce_max_sync(FULLMASK, __float_as_uint(bestv));
        float wmf = __uint_as_float(wm);
        unsigned cand = 0x7FFFFFFFu;
#pragma unroll
        for (int sl = 7; sl >= 0; sl--)
            cand = (dist[sl] == wmf) ? (unsigned)(t + (sl << 10)) : cand;
        cand = __reduce_min_sync(FULLMASK, cand);

        if (lane == 0) { s_val[s & 1][warp] = wm; s_idx[s & 1][warp] = (int)cand; }
        __syncthreads();

        unsigned v = s_val[s & 1][lane];
        int      ci = s_idx[s & 1][lane];
        unsigned gm = __reduce_max_sync(FULLMASK, v);
        unsigned c2 = (v == gm) ? (unsigned)ci : 0x7FFFFFFFu;
        int widx = (int)__reduce_min_sync(FULLMASK, c2);

        cx = X[widx * 3 + 0];
        cy = X[widx * 3 + 1];
        cz = X[widx * 3 + 2];
        if (t == 0) {
            float* o = g_newxyz + (size_t)(b * SS + s + 1) * 3;
            o[0] = cx; o[1] = cy; o[2] = cz;
        }
    }
}

// =====================================================================
// K2: kNN (K=32) + group stats. 128 blocks x 1024 threads, warp per
// query (4 queries/warp, processed as 2 pairs sharing candidate loads).
// Candidates pre-packed in smem as f32x2 pairs: sxy[j]={x2,y2},
// szw[j]={z2,sq2} for candidates (2j, 2j+1) -> zero pk2 in the scan and
// half the smem traffic. key = (orderable(d) << 13) | idx; the merges
// keep the exact 32 smallest (d,idx) keys, so the selected SET ==
// lax.top_k (insertion order / lane pairing irrelevant; `<=` only
// over-admits exact ties which merges drop).
// =====================================================================
__device__ __forceinline__ ull u64min(ull a, ull b) { return a < b ? a : b; }
__device__ __forceinline__ ull u64max(ull a, ull b) { return a < b ? b : a; }
__device__ __forceinline__ ull makekey(float d, int idx) {
    unsigned ub = __float_as_uint(d);
    ub ^= ((unsigned)((int)ub >> 31)) | 0x80000000u;
    return ((ull)ub << 13) | (unsigned)idx;
}
__device__ __forceinline__ float kth2kd(ull kth) {
    unsigned ub = (unsigned)(kth >> 13);
    unsigned db = (ub >> 31) ? (ub ^ 0x80000000u) : ~ub;
    return __uint_as_float(db);
}
__device__ __forceinline__ ull sort32(ull key, int lane)
{
#pragma unroll
    for (int k = 2; k <= 32; k <<= 1) {
#pragma unroll
        for (int j = k >> 1; j > 0; j >>= 1) {
            ull other = __shfl_xor_sync(FULLMASK, key, j);
            bool up = ((lane & k) == 0);
            bool takeMin = (((lane & j) == 0) == up);
            key = takeMin ? u64min(key, other) : u64max(key, other);
        }
    }
    return key;
}
__device__ __forceinline__ ull merge32(ull key, ull buf, int lane)
{
    buf = sort32(buf, lane);
    ull rev = __shfl_sync(FULLMASK, buf, 31 - lane);
    key = u64min(key, rev);
#pragma unroll
    for (int j = 16; j > 0; j >>= 1) {
        ull other = __shfl_xor_sync(FULLMASK, key, j);
        bool takeMin = ((lane & j) == 0);
        key = takeMin ? u64min(key, other) : u64max(key, other);
    }
    return key;
}
__device__ __forceinline__ void push_chunk(ull ck, unsigned m, int lane,
                                           ull& key, float& kd,
                                           ull& buf, int& bcnt)
{
    int cnt = __popc(m);
    int r = lane - bcnt;
    bool take = (r >= 0) && (r < cnt);
    unsigned pos = __fns(m, 0, take ? (r + 1) : 1);
    ull got = __shfl_sync(FULLMASK, ck, pos & 31);
    if (take) buf = got;
    bcnt += cnt;
    if (bcnt >= 32) {
        key = merge32(key, buf, lane);
        ull kth = __shfl_sync(FULLMASK, key, 31);
        kd = kth2kd(kth);
        int left = bcnt - 32;
        buf = ~0ull;
        if (left) {   // re-push overflow candidates (extras are harmless)
            int start = cnt - left;
            bool tk2 = lane < left;
            unsigned pos2 = __fns(m, 0, tk2 ? (start + lane + 1) : 1);
            ull got2 = __shfl_sync(FULLMASK, ck, pos2 & 31);
            if (tk2) buf = got2;
        }
        bcnt = left;
    }
}

__global__ void __launch_bounds__(1024) knn_kernel(const float* __restrict__ xyz)
{
    extern __shared__ ulonglong2 sm2[];
    ulonglong2* sxy = sm2;                 // [NN/2] {x2, y2}
    ulonglong2* szw = sm2 + NN / 2;        // [NN/2] {z2, sq2}
    __shared__ double s_p1[32], s_p2[32];

    const int b  = blockIdx.x >> 3;        // 8 query-chunks (128 q) per batch
    const int qc = blockIdx.x & 7;
    const float* X = xyz + (size_t)b * NN * 3;

    for (int j = threadIdx.x; j < NN / 2; j += 1024) {
        const float* p = X + 6 * j;
        float x0 = p[0], y0 = p[1], z0 = p[2];
        float x1 = p[3], y1 = p[4], z1 = p[5];
        float sq0 = __fadd_rn(__fadd_rn(__fmul_rn(x0, x0), __fmul_rn(y0, y0)),
                              __fmul_rn(z0, z0));
        float sq1 = __fadd_rn(__fadd_rn(__fmul_rn(x1, x1), __fmul_rn(y1, y1)),
                              __fmul_rn(z1, z1));
        sxy[j] = make_ulonglong2(pk2(x0, x1), pk2(y0, y1));
        szw[j] = make_ulonglong2(pk2(z0, z1), pk2(sq0, sq1));
    }
    __syncthreads();

    const int warp = threadIdx.x >> 5;
    const int lane = threadIdx.x & 31;
    const ull m2two = pk2(-2.0f, -2.0f);

    double acc1 = 0.0, acc2 = 0.0;         // meaningful on lane 0 only

    for (int qp = 0; qp < 2; qp++) {
        const int s0 = qc * 128 + warp * 4 + 2 * qp;
        const int s1 = s0 + 1;

        const float* cen0 = g_newxyz + (size_t)(b * SS + s0) * 3;
        const float* cen1 = g_newxyz + (size_t)(b * SS + s1) * 3;
        const float ax = cen0[0], ay = cen0[1], az = cen0[2];
        const float bx = cen1[0], by = cen1[1], bz = cen1[2];
        const float asq = __fadd_rn(__fadd_rn(__fmul_rn(ax, ax), __fmul_rn(ay, ay)),
                                    __fmul_rn(az, az));
        const float bsq = __fadd_rn(__fadd_rn(__fmul_rn(bx, bx), __fmul_rn(by, by)),
                                    __fmul_rn(bz, bz));
        const ull aX2 = pk2(ax, ax), aY2 = pk2(ay, ay), aZ2 = pk2(az, az);
        const ull aS2 = pk2(asq, asq);
        const ull bX2 = pk2(bx, bx), bY2 = pk2(by, by), bZ2 = pk2(bz, bz);
        const ull bS2 = pk2(bsq, bsq);

        // init from candidates 0..63 (lane pair = cands 2lane, 2lane+1)
        ull key0, key1;
        float kd0, kd1;
        {
            ulonglong2 A = sxy[lane];
            ulonglong2 B = szw[lane];
            ull dot0 = add2(add2(mul2(A.x, aX2), mul2(A.y, aY2)), mul2(B.x, aZ2));
            ull dd0 = add2(add2(mul2(m2two, dot0), aS2), B.y);
            ull dot1 = add2(add2(mul2(A.x, bX2), mul2(A.y, bY2)), mul2(B.x, bZ2));
            ull dd1 = add2(add2(mul2(m2two, dot1), bS2), B.y);
            float de, dq;
            upk2(de, dq, dd0);
            key0 = sort32(makekey(de, 2 * lane), lane);
            key0 = merge32(key0, makekey(dq, 2 * lane + 1), lane);
            kd0 = kth2kd(__shfl_sync(FULLMASK, key0, 31));
            upk2(de, dq, dd1);
            key1 = sort32(makekey(de, 2 * lane), lane);
            key1 = merge32(key1, makekey(dq, 2 * lane + 1), lane);
            kd1 = kth2kd(__shfl_sync(FULLMASK, key1, 31));
        }
        ull buf0 = ~0ull, buf1 = ~0ull;
        int bc0 = 0, bc1 = 0;

        // scan: 64 candidates per chunk, shared across both queries
        for (int jb = 32; jb < NN / 2; jb += 32) {
            const int j = jb + lane;               // cands 2j, 2j+1
            ulonglong2 A = sxy[j];
            ulonglong2 B = szw[j];
            ull dot0 = add2(add2(mul2(A.x, aX2), mul2(A.y, aY2)), mul2(B.x, aZ2));
            ull dd0 = add2(add2(mul2(m2two, dot0), aS2), B.y);
            ull dot1 = add2(add2(mul2(A.x, bX2), mul2(A.y, bY2)), mul2(B.x, bZ2));
            ull dd1 = add2(add2(mul2(m2two, dot1), bS2), B.y);
            float d0e, d0o, d1e, d1o;
            upk2(d0e, d0o, dd0);
            upk2(d1e, d1o, dd1);
            bool hit = (d0e <= kd0) | (d0o <= kd0) | (d1e <= kd1) | (d1o <= kd1);
            if (__any_sync(FULLMASK, hit)) {
                unsigned m;
                m = __ballot_sync(FULLMASK, d0e <= kd0);
                if (m) push_chunk(makekey(d0e, 2 * j), m, lane, key0, kd0, buf0, bc0);
                m = __ballot_sync(FULLMASK, d0o <= kd0);
                if (m) push_chunk(makekey(d0o, 2 * j + 1), m, lane, key0, kd0, buf0, bc0);
                m = __ballot_sync(FULLMASK, d1e <= kd1);
                if (m) push_chunk(makekey(d1e, 2 * j), m, lane, key1, kd1, buf1, bc1);
                m = __ballot_sync(FULLMASK, d1o <= kd1);
                if (m) push_chunk(makekey(d1o, 2 * j + 1), m, lane, key1, kd1, buf1, bc1);
            }
        }
        if (bc0 > 0) key0 = merge32(key0, buf0, lane);
        if (bc1 > 0) key1 = merge32(key1, buf1, lane);

        // ----- group stats for both queries -----
#pragma unroll
        for (int q = 0; q < 2; q++) {
            ull key = q ? key1 : key0;
            float cx = q ? bx : ax, cy = q ? by : ay, cz = q ? bz : az;
            int sq = q ? s1 : s0;
            int ki = (int)(key & 0x1FFFull);
            ulonglong2 P1 = sxy[ki >> 1];
            ulonglong2 P2 = szw[ki >> 1];
            float xl, xh, yl, yh, zl, zh;
            upk2(xl, xh, P1.x);
            upk2(yl, yh, P1.y);
            upk2(zl, zh, P2.x);
            float px = (ki & 1) ? xh : xl;
            float py = (ki & 1) ? yh : yl;
            float pz = (ki & 1) ? zh : zl;
            float dx = __fsub_rn(px, cx);
            float dy = __fsub_rn(py, cy);
            float dz = __fsub_rn(pz, cz);
            float sdx = dx, sdy = dy, sdz = dz;
            float mdx = dx, mdy = dy, mdz = dz;
            float t1 = dx + dy + dz;
            float t2 = dx * dx + dy * dy + dz * dz;
#pragma unroll
            for (int o = 16; o; o >>= 1) {
                sdx += __shfl_down_sync(FULLMASK, sdx, o);
                sdy += __shfl_down_sync(FULLMASK, sdy, o);
                sdz += __shfl_down_sync(FULLMASK, sdz, o);
                mdx = fmaxf(mdx, __shfl_down_sync(FULLMASK, mdx, o));
                mdy = fmaxf(mdy, __shfl_down_sync(FULLMASK, mdy, o));
                mdz = fmaxf(mdz, __shfl_down_sync(FULLMASK, mdz, o));
                t1 += __shfl_down_sync(FULLMASK, t1, o);
                t2 += __shfl_down_sync(FULLMASK, t2, o);
            }
            if (lane == 0) {
                int ix = (b * SS + sq) * 3;
                g_gsum[ix] = sdx; g_gsum[ix + 1] = sdy; g_gsum[ix + 2] = sdz;
                g_gmax[ix] = mdx; g_gmax[ix + 1] = mdy; g_gmax[ix + 2] = mdz;
                acc1 += (double)t1;
                acc2 += (double)t2;
            }
        }
    }

    // one atomicAdd pair per block
    if (lane == 0) { s_p1[warp] = acc1; s_p2[warp] = acc2; }
    __syncthreads();
    if (threadIdx.x == 0) {
        double a = 0.0, c = 0.0;
        for (int w = 0; w < 32; w++) { a += s_p1[w]; c += s_p2[w]; }
        atomicAdd(&g_acc[0], a);
        atomicAdd(&g_acc[1], c);
    }
}

// =====================================================================
// K3a: lc build — 64 blocks x 256 threads.
// =====================================================================
__global__ void __launch_bounds__(256) finalize1_kernel()
{
    const int idx = blockIdx.x * 256 + threadIdx.x;   // 0..16383
    double M = (double)BB * SS * KK * 3;
    double var = (g_acc[1] - g_acc[0] * g_acc[0] / M) / (M - 1.0);  // ddof=1
    const float se = (float)sqrt(var) + 1e-5f;

    int b = idx >> 10, s = idx & (SS - 1);
    const float* gm = g_gmax + idx * 3;
    const float* gs = g_gsum + idx * 3;
    const float* cn = g_newxyz + idx * 3;
#pragma unroll
    for (int c = 0; c < 3; c++) {
        float mx = __fdiv_rn(gm[c], se);
        float mn = __fdiv_rn(__fdiv_rn(gs[c], 32.0f), se);
        g_lc[(b * 6 + c) * SS + s] = __fadd_rn(mx, mn);
    }
#pragma unroll
    for (int c = 0; c < 3; c++) {
        float v = cn[c];
        g_lc[(b * 6 + 3 + c) * SS + s] = v + v;
    }
}

// =====================================================================
// K3b: BN1 stats (fused 6-channel passes), cdist with on-the-fly
// normalize+relu, BN2. Single block.
// =====================================================================
__global__ void __launch_bounds__(1024) finalize2_kernel(
    const float* __restrict__ bn1g, const float* __restrict__ bn1b,
    const float* __restrict__ bn2g, const float* __restrict__ bn2b,
    float* __restrict__ out)
{
    const int t = threadIdx.x;
    const int lane = t & 31, warp = t >> 5;

    __shared__ float s_part[6][32];
    __shared__ float s_mean[6], s_den[6], s_g[6], s_bt[6];
    __shared__ float s_tf[BB * 36];
    __shared__ float s_m2[36], s_v2[36];

    // pass A: all 6 channel sums in one sweep
    float sum[6] = {0, 0, 0, 0, 0, 0};
    for (int i = t; i < BB * SS; i += 1024) {
        int b = i >> 10, s = i & 1023;
        const float* base = g_lc + (b * 6) * SS + s;
#pragma unroll
        for (int c = 0; c < 6; c++) sum[c] += base[c * SS];
    }
#pragma unroll
    for (int c = 0; c < 6; c++) {
#pragma unroll
        for (int o = 16; o; o >>= 1) sum[c] += __shfl_down_sync(FULLMASK, sum[c], o);
        if (lane == 0) s_part[c][warp] = sum[c];
    }
    __syncthreads();
    if (t < 6) {
        float tot = 0.0f;
        for (int w = 0; w < 32; w++) tot += s_part[t][w];
        s_mean[t] = tot / (float)(BB * SS);
        s_g[t] = bn1g[t];
        s_bt[t] = bn1b[t];
    }
    __syncthreads();

    // pass B: all 6 channel vars in one sweep
    float m0 = s_mean[0], m1 = s_mean[1], m2 = s_mean[2];
    float m3 = s_mean[3], m4 = s_mean[4], m5 = s_mean[5];
    float vs[6] = {0, 0, 0, 0, 0, 0};
    for (int i = t; i < BB * SS; i += 1024) {
        int b = i >> 10, s = i & 1023;
        const float* base = g_lc + (b * 6) * SS + s;
        float d0 = base[0 * SS] - m0; vs[0] += d0 * d0;
        float d1 = base[1 * SS] - m1; vs[1] += d1 * d1;
        float d2 = base[2 * SS] - m2; vs[2] += d2 * d2;
        float d3 = base[3 * SS] - m3; vs[3] += d3 * d3;
        float d4 = base[4 * SS] - m4; vs[4] += d4 * d4;
        float d5 = base[5 * SS] - m5; vs[5] += d5 * d5;
    }
#pragma unroll
    for (int c = 0; c < 6; c++) {
#pragma unroll
        for (int o = 16; o; o >>= 1) vs[c] += __shfl_down_sync(FULLMASK, vs[c], o);
        if (lane == 0) s_part[c][warp] = vs[c];
    }
    __syncthreads();
    if (t < 6) {
        float tot = 0.0f;
        for (int w = 0; w < 32; w++) tot += s_part[t][w];
        float var = tot / (float)(BB * SS);    // biased, as in reference
        s_den[t] = sqrtf(var + 1e-5f);
    }
    if (t < BB * 6) {
        int b = t / 6, c = t % 6;
        s_tf[b * 36 + c * 6 + c] = 0.0f;
    }
    __syncthreads();

    // cdist with on-the-fly BN1 normalize + relu
    for (int task = warp; task < BB * 15; task += 32) {
        int b = task / 15, pr = task % 15;
        int i = 0, j = 0, p = pr;
        for (i = 0; i < 5; i++) {
            int row = 5 - i;
            if (p < row) { j = i + 1 + p; break; }
            p -= row;
        }
        const float* A  = g_lc + (b * 6 + i) * SS;
        const float* Bp = g_lc + (b * 6 + j) * SS;
        float mi = s_mean[i], di = s_den[i], gi = s_g[i], bi = s_bt[i];
        float mj = s_mean[j], dj = s_den[j], gj = s_g[j], bj = s_bt[j];
        float part = 0.0f;
        for (int s = lane; s < SS; s += 32) {
            float a = fmaxf((A[s] - mi) / di * gi + bi, 0.0f);
            float c = fmaxf((Bp[s] - mj) / dj * gj + bj, 0.0f);
            float d = a - c;
            part += d * d;
        }
#pragma unroll
        for (int o = 16; o; o >>= 1) part += __shfl_down_sync(FULLMASK, part, o);
        if (lane == 0) {
            float v = part > 0.0f ? sqrtf(part) : 0.0f;   // zero-safe
            s_tf[b * 36 + i * 6 + j] = v;
            s_tf[b * 36 + j * 6 + i] = v;
        }
    }
    __syncthreads();

    // BN2 over batch (16) per feature (36)
    if (t < 36) {
        float m = 0.0f;
        for (int b = 0; b < BB; b++) m += s_tf[b * 36 + t];
        m /= (float)BB;
        float v = 0.0f;
        for (int b = 0; b < BB; b++) {
            float d = s_tf[b * 36 + t] - m;
            v += d * d;
        }
        v /= (float)BB;
        s_m2[t] = m; s_v2[t] = v;
    }
    __syncthreads();
    if (t < BB * 36) {
        int b = t / 36, f = t % 36;
        float x = s_tf[b * 36 + f];
        float y = (x - s_m2[f]) / sqrtf(s_v2[f] + 1e-5f) * bn2g[f] + bn2b[f];
        out[t] = fmaxf(y, 0.0f);
    }
}

// =====================================================================
extern "C" void kernel_launch(void* const* d_in, const int* in_sizes, int n_in,
                              void* d_out, int out_size)
{
    const float* xyz  = (const float*)d_in[0];
    const float* bn1g = (const float*)d_in[1];
    const float* bn1b = (const float*)d_in[2];
    const float* bn2g = (const float*)d_in[3];
    const float* bn2b = (const float*)d_in[4];
    float* out = (float*)d_out;

    // idempotent host-side attribute set (capture-safe)
    cudaFuncSetAttribute(knn_kernel, cudaFuncAttributeMaxDynamicSharedMemorySize,
                         NN * 16);

    fps_kernel<<<BB, 1024>>>(xyz);
    knn_kernel<<<BB * 8, 1024, NN * 16>>>(xyz);
    finalize1_kernel<<<64, 256>>>();
    finalize2_kernel<<<1, 1024>>>(bn1g, bn1b, bn2g, bn2b, out);
}

// round 10
// speedup vs baseline: 1.5137x; 1.1257x over previous
#include <cuda_runtime.h>
#include <cuda_bf16.h>

#define BB 16
#define NN 8192
#define SS 1024
#define KK 32
#define FULLMASK 0xFFFFFFFFu
typedef unsigned long long ull;

// ---------------- scratch (no allocs allowed) ----------------
__device__ float  g_newxyz[BB * SS * 3];   // FPS-selected centers
__device__ float  g_gmax[BB * SS * 3];     // max over K of diff, per coord
__device__ float  g_gsum[BB * SS * 3];     // sum over K of diff, per coord
__device__ double g_acc[2];                // sum(diff), sum(diff^2) for global std
__device__ float  g_lc[BB * 6 * SS];       // pooled features (raw, pre-BN1)
__device__ volatile int g_prog[BB];        // centroids published per batch
__device__ double g_ch[12];                // BN1 per-channel sum[6], sumsq[6]
__device__ float  g_tf[BB * 36];           // cdist features pre-BN2

// ---------------- f32x2 helpers (Blackwell packed fp32) ----------------
__device__ __forceinline__ ull pk2(float lo, float hi) {
    ull r;
    asm("mov.b64 %0, {%1, %2};" : "=l"(r) : "f"(lo), "f"(hi));
    return r;
}
__device__ __forceinline__ void upk2(float& lo, float& hi, ull v) {
    asm("mov.b64 {%0, %1}, %2;" : "=f"(lo), "=f"(hi) : "l"(v));
}
__device__ __forceinline__ ull add2(ull a, ull b) {
    ull r;
    asm("add.rn.f32x2 %0, %1, %2;" : "=l"(r) : "l"(a), "l"(b));
    return r;
}
__device__ __forceinline__ ull mul2(ull a, ull b) {
    ull r;
    asm("mul.rn.f32x2 %0, %1, %2;" : "=l"(r) : "l"(a), "l"(b));
    return r;
}

// ---------------- top-k machinery (R9, proven) ----------------
__device__ __forceinline__ ull u64min(ull a, ull b) { return a < b ? a : b; }
__device__ __forceinline__ ull u64max(ull a, ull b) { return a < b ? b : a; }
__device__ __forceinline__ ull makekey(float d, int idx) {
    unsigned ub = __float_as_uint(d);
    ub ^= ((unsigned)((int)ub >> 31)) | 0x80000000u;
    return ((ull)ub << 13) | (unsigned)idx;
}
__device__ __forceinline__ float kth2kd(ull kth) {
    unsigned ub = (unsigned)(kth >> 13);
    unsigned db = (ub >> 31) ? (ub ^ 0x80000000u) : ~ub;
    return __uint_as_float(db);
}
__device__ __forceinline__ ull sort32(ull key, int lane)
{
#pragma unroll
    for (int k = 2; k <= 32; k <<= 1) {
#pragma unroll
        for (int j = k >> 1; j > 0; j >>= 1) {
            ull other = __shfl_xor_sync(FULLMASK, key, j);
            bool up = ((lane & k) == 0);
            bool takeMin = (((lane & j) == 0) == up);
            key = takeMin ? u64min(key, other) : u64max(key, other);
        }
    }
    return key;
}
__device__ __forceinline__ ull merge32(ull key, ull buf, int lane)
{
    buf = sort32(buf, lane);
    ull rev = __shfl_sync(FULLMASK, buf, 31 - lane);
    key = u64min(key, rev);
#pragma unroll
    for (int j = 16; j > 0; j >>= 1) {
        ull other = __shfl_xor_sync(FULLMASK, key, j);
        bool takeMin = ((lane & j) == 0);
        key = takeMin ? u64min(key, other) : u64max(key, other);
    }
    return key;
}
__device__ __forceinline__ void push_chunk(ull ck, unsigned m, int lane,
                                           ull& key, float& kd,
                                           ull& buf, int& bcnt)
{
    int cnt = __popc(m);
    int r = lane - bcnt;
    bool take = (r >= 0) && (r < cnt);
    unsigned pos = __fns(m, 0, take ? (r + 1) : 1);
    ull got = __shfl_sync(FULLMASK, ck, pos & 31);
    if (take) buf = got;
    bcnt += cnt;
    if (bcnt >= 32) {
        key = merge32(key, buf, lane);
        ull kth = __shfl_sync(FULLMASK, key, 31);
        kd = kth2kd(kth);
        int left = bcnt - 32;
        buf = ~0ull;
        if (left) {   // re-push overflow candidates (extras are harmless)
            int start = cnt - left;
            bool tk2 = lane < left;
            unsigned pos2 = __fns(m, 0, tk2 ? (start + lane + 1) : 1);
            ull got2 = __shfl_sync(FULLMASK, ck, pos2 & 31);
            if (tk2) buf = got2;
        }
        bcnt = left;
    }
}

// =====================================================================
// Fused producer/consumer kernel. 144 blocks x 1024 threads (all
// resident in wave 1 on 148 SMs -> spin-wait is deadlock-free).
//   blocks 0..15   : FPS for batch b (exact R4 math), publishes
//                    g_prog[b] every 16 steps (threadfence-ordered).
//   blocks 16..143 : kNN (R9 pairing); each warp spin-waits until its
//                    pair's centroids are published, then scans.
// Results are bit-identical to the sequential version.
// =====================================================================
__global__ void __launch_bounds__(1024) fused_kernel(const float* __restrict__ xyz)
{
    extern __shared__ char dyn_smem[];
    const int t = threadIdx.x;
    const int lane = t & 31, warp = t >> 5;

    if (blockIdx.x < BB) {
        // ---------------- FPS path ----------------
        const int b = blockIdx.x;
        const float* X = xyz + (size_t)b * NN * 3;

        ull px2[4], py2[4], pz2[4];
        float dist[8];
#pragma unroll
        for (int i = 0; i < 4; i++) {
            int p0 = t + 1024 * (2 * i);
            int p1 = t + 1024 * (2 * i + 1);
            px2[i] = pk2(X[p0 * 3 + 0], X[p1 * 3 + 0]);
            py2[i] = pk2(X[p0 * 3 + 1], X[p1 * 3 + 1]);
            pz2[i] = pk2(X[p0 * 3 + 2], X[p1 * 3 + 2]);
            dist[2 * i] = 1e10f;
            dist[2 * i + 1] = 1e10f;
        }

        __shared__ unsigned s_val[2][32];
        __shared__ int      s_idx[2][32];

        float cx = X[0], cy = X[1], cz = X[2];   // sample 0 = point 0
        if (t == 0) {
            float* o = g_newxyz + (size_t)(b * SS) * 3;
            o[0] = cx; o[1] = cy; o[2] = cz;
        }

        for (int s = 0; s < SS - 1; s++) {
            const ull ncx2 = pk2(-cx, -cx);
            const ull ncy2 = pk2(-cy, -cy);
            const ull ncz2 = pk2(-cz, -cz);

            float bestv = -1.0f;
#pragma unroll
            for (int i = 0; i < 4; i++) {
                ull dx2 = add2(px2[i], ncx2);
                ull dy2 = add2(py2[i], ncy2);
                ull dz2 = add2(pz2[i], ncz2);
                ull d2 = add2(add2(mul2(dx2, dx2), mul2(dy2, dy2)), mul2(dz2, dz2));
                float d0, d1;
                upk2(d0, d1, d2);
                float n0 = fminf(dist[2 * i], d0);
                float n1 = fminf(dist[2 * i + 1], d1);
                dist[2 * i] = n0;
                dist[2 * i + 1] = n1;
                bestv = fmaxf(bestv, fmaxf(n0, n1));
            }

            unsigned wm = __reduce_max_sync(FULLMASK, __float_as_uint(bestv));
            float wmf = __uint_as_float(wm);
            unsigned cand = 0x7FFFFFFFu;
#pragma unroll
            for (int sl = 7; sl >= 0; sl--)
                cand = (dist[sl] == wmf) ? (unsigned)(t + (sl << 10)) : cand;
            cand = __reduce_min_sync(FULLMASK, cand);

            if (lane == 0) { s_val[s & 1][warp] = wm; s_idx[s & 1][warp] = (int)cand; }
            __syncthreads();

            unsigned v = s_val[s & 1][lane];
            int      ci = s_idx[s & 1][lane];
            unsigned gm = __reduce_max_sync(FULLMASK, v);
            unsigned c2 = (v == gm) ? (unsigned)ci : 0x7FFFFFFFu;
            int widx = (int)__reduce_min_sync(FULLMASK, c2);

            cx = X[widx * 3 + 0];
            cy = X[widx * 3 + 1];
            cz = X[widx * 3 + 2];
            if (t == 0) {
                float* o = g_newxyz + (size_t)(b * SS + s + 1) * 3;
                o[0] = cx; o[1] = cy; o[2] = cz;
                if ((s & 15) == 15) {           // publish progress
                    __threadfence();
                    g_prog[b] = s + 2;
                }
            }
        }
        if (t == 0) {                           // final publish
            __threadfence();
            g_prog[b] = SS;
        }
        return;
    }

    // ---------------- kNN path ----------------
    ulonglong2* sxy = (ulonglong2*)dyn_smem;         // [NN/2] {x2, y2}
    ulonglong2* szw = (ulonglong2*)dyn_smem + NN / 2; // [NN/2] {z2, sq2}
    __shared__ double s_p1[32], s_p2[32];

    const int kb = blockIdx.x - BB;
    const int b  = kb >> 3;                    // 8 blocks per batch
    const int qc = kb & 7;
    const float* X = xyz + (size_t)b * NN * 3;

    for (int j = t; j < NN / 2; j += 1024) {
        const float* p = X + 6 * j;
        float x0 = p[0], y0 = p[1], z0 = p[2];
        float x1 = p[3], y1 = p[4], z1 = p[5];
        float sq0 = __fadd_rn(__fadd_rn(__fmul_rn(x0, x0), __fmul_rn(y0, y0)),
                              __fmul_rn(z0, z0));
        float sq1 = __fadd_rn(__fadd_rn(__fmul_rn(x1, x1), __fmul_rn(y1, y1)),
                              __fmul_rn(z1, z1));
        sxy[j] = make_ulonglong2(pk2(x0, x1), pk2(y0, y1));
        szw[j] = make_ulonglong2(pk2(z0, z1), pk2(sq0, sq1));
    }
    __syncthreads();

    const ull m2two = pk2(-2.0f, -2.0f);
    const int g = qc * 32 + warp;              // 0..255 per batch

    double acc1 = 0.0, acc2 = 0.0;             // meaningful on lane 0 only

    for (int qp = 0; qp < 2; qp++) {
        const int s0 = (qp ? 512 : 0) + 2 * g;
        const int s1 = s0 + 1;

        // wait for fps to publish centroids s0, s1
        while (g_prog[b] < s1 + 1) __nanosleep(200);
        __threadfence();

        const float* cen0 = g_newxyz + (size_t)(b * SS + s0) * 3;
        const float* cen1 = g_newxyz + (size_t)(b * SS + s1) * 3;
        const float ax = cen0[0], ay = cen0[1], az = cen0[2];
        const float bx = cen1[0], by = cen1[1], bz = cen1[2];
        const float asq = __fadd_rn(__fadd_rn(__fmul_rn(ax, ax), __fmul_rn(ay, ay)),
                                    __fmul_rn(az, az));
        const float bsq = __fadd_rn(__fadd_rn(__fmul_rn(bx, bx), __fmul_rn(by, by)),
                                    __fmul_rn(bz, bz));
        const ull aX2 = pk2(ax, ax), aY2 = pk2(ay, ay), aZ2 = pk2(az, az);
        const ull aS2 = pk2(asq, asq);
        const ull bX2 = pk2(bx, bx), bY2 = pk2(by, by), bZ2 = pk2(bz, bz);
        const ull bS2 = pk2(bsq, bsq);

        ull key0, key1;
        float kd0, kd1;
        {
            ulonglong2 A = sxy[lane];
            ulonglong2 B = szw[lane];
            ull dot0 = add2(add2(mul2(A.x, aX2), mul2(A.y, aY2)), mul2(B.x, aZ2));
            ull dd0 = add2(add2(mul2(m2two, dot0), aS2), B.y);
            ull dot1 = add2(add2(mul2(A.x, bX2), mul2(A.y, bY2)), mul2(B.x, bZ2));
            ull dd1 = add2(add2(mul2(m2two, dot1), bS2), B.y);
            float de, dq;
            upk2(de, dq, dd0);
            key0 = sort32(makekey(de, 2 * lane), lane);
            key0 = merge32(key0, makekey(dq, 2 * lane + 1), lane);
            kd0 = kth2kd(__shfl_sync(FULLMASK, key0, 31));
            upk2(de, dq, dd1);
            key1 = sort32(makekey(de, 2 * lane), lane);
            key1 = merge32(key1, makekey(dq, 2 * lane + 1), lane);
            kd1 = kth2kd(__shfl_sync(FULLMASK, key1, 31));
        }
        ull buf0 = ~0ull, buf1 = ~0ull;
        int bc0 = 0, bc1 = 0;

        for (int jb = 32; jb < NN / 2; jb += 32) {
            const int j = jb + lane;           // cands 2j, 2j+1
            ulonglong2 A = sxy[j];
            ulonglong2 B = szw[j];
            ull dot0 = add2(add2(mul2(A.x, aX2), mul2(A.y, aY2)), mul2(B.x, aZ2));
            ull dd0 = add2(add2(mul2(m2two, dot0), aS2), B.y);
            ull dot1 = add2(add2(mul2(A.x, bX2), mul2(A.y, bY2)), mul2(B.x, bZ2));
            ull dd1 = add2(add2(mul2(m2two, dot1), bS2), B.y);
            float d0e, d0o, d1e, d1o;
            upk2(d0e, d0o, dd0);
            upk2(d1e, d1o, dd1);
            bool hit = (d0e <= kd0) | (d0o <= kd0) | (d1e <= kd1) | (d1o <= kd1);
            if (__any_sync(FULLMASK, hit)) {
                unsigned m;
                m = __ballot_sync(FULLMASK, d0e <= kd0);
                if (m) push_chunk(makekey(d0e, 2 * j), m, lane, key0, kd0, buf0, bc0);
                m = __ballot_sync(FULLMASK, d0o <= kd0);
                if (m) push_chunk(makekey(d0o, 2 * j + 1), m, lane, key0, kd0, buf0, bc0);
                m = __ballot_sync(FULLMASK, d1e <= kd1);
                if (m) push_chunk(makekey(d1e, 2 * j), m, lane, key1, kd1, buf1, bc1);
                m = __ballot_sync(FULLMASK, d1o <= kd1);
                if (m) push_chunk(makekey(d1o, 2 * j + 1), m, lane, key1, kd1, buf1, bc1);
            }
        }
        if (bc0 > 0) key0 = merge32(key0, buf0, lane);
        if (bc1 > 0) key1 = merge32(key1, buf1, lane);

        // ----- group stats for both queries -----
#pragma unroll
        for (int q = 0; q < 2; q++) {
            ull key = q ? key1 : key0;
            float cx = q ? bx : ax, cy = q ? by : ay, cz = q ? bz : az;
            int sq = q ? s1 : s0;
            int ki = (int)(key & 0x1FFFull);
            ulonglong2 P1 = sxy[ki >> 1];
            ulonglong2 P2 = szw[ki >> 1];
            float xl, xh, yl, yh, zl, zh;
            upk2(xl, xh, P1.x);
            upk2(yl, yh, P1.y);
            upk2(zl, zh, P2.x);
            float px = (ki & 1) ? xh : xl;
            float py = (ki & 1) ? yh : yl;
            float pz = (ki & 1) ? zh : zl;
            float dx = __fsub_rn(px, cx);
            float dy = __fsub_rn(py, cy);
            float dz = __fsub_rn(pz, cz);
            float sdx = dx, sdy = dy, sdz = dz;
            float mdx = dx, mdy = dy, mdz = dz;
            float t1 = dx + dy + dz;
            float t2 = dx * dx + dy * dy + dz * dz;
#pragma unroll
            for (int o = 16; o; o >>= 1) {
                sdx += __shfl_down_sync(FULLMASK, sdx, o);
                sdy += __shfl_down_sync(FULLMASK, sdy, o);
                sdz += __shfl_down_sync(FULLMASK, sdz, o);
                mdx = fmaxf(mdx, __shfl_down_sync(FULLMASK, mdx, o));
                mdy = fmaxf(mdy, __shfl_down_sync(FULLMASK, mdy, o));
                mdz = fmaxf(mdz, __shfl_down_sync(FULLMASK, mdz, o));
                t1 += __shfl_down_sync(FULLMASK, t1, o);
                t2 += __shfl_down_sync(FULLMASK, t2, o);
            }
            if (lane == 0) {
                int ix = (b * SS + sq) * 3;
                g_gsum[ix] = sdx; g_gsum[ix + 1] = sdy; g_gsum[ix + 2] = sdz;
                g_gmax[ix] = mdx; g_gmax[ix + 1] = mdy; g_gmax[ix + 2] = mdz;
                acc1 += (double)t1;
                acc2 += (double)t2;
            }
        }
    }

    if (lane == 0) { s_p1[warp] = acc1; s_p2[warp] = acc2; }
    __syncthreads();
    if (t == 0) {
        double a = 0.0, c = 0.0;
        for (int w = 0; w < 32; w++) { a += s_p1[w]; c += s_p2[w]; }
        atomicAdd(&g_acc[0], a);
        atomicAdd(&g_acc[1], c);
    }
}

// =====================================================================
// K3a: lc build (64 blocks) + BN1 channel sum/sumsq via double atomics.
// =====================================================================
__global__ void __launch_bounds__(256) finalize1_kernel()
{
    const int t = threadIdx.x;
    const int lane = t & 31, warp = t >> 5;
    const int idx = blockIdx.x * 256 + t;     // 0..16383
    __shared__ float s_red[12][8];

    double M = (double)BB * SS * KK * 3;
    double var = (g_acc[1] - g_acc[0] * g_acc[0] / M) / (M - 1.0);  // ddof=1
    const float se = (float)sqrt(var) + 1e-5f;

    int b = idx >> 10, s = idx & (SS - 1);
    const float* gm = g_gmax + idx * 3;
    const float* gs = g_gsum + idx * 3;
    const float* cn = g_newxyz + idx * 3;
    float v[6];
#pragma unroll
    for (int c = 0; c < 3; c++) {
        float mx = __fdiv_rn(gm[c], se);
        float mn = __fdiv_rn(__fdiv_rn(gs[c], 32.0f), se);
        v[c] = __fadd_rn(mx, mn);
        g_lc[(b * 6 + c) * SS + s] = v[c];
    }
#pragma unroll
    for (int c = 0; c < 3; c++) {
        float w = cn[c];
        v[3 + c] = w + w;
        g_lc[(b * 6 + 3 + c) * SS + s] = v[3 + c];
    }

    float sm[12];
#pragma unroll
    for (int c = 0; c < 6; c++) { sm[c] = v[c]; sm[6 + c] = v[c] * v[c]; }
#pragma unroll
    for (int k = 0; k < 12; k++) {
#pragma unroll
        for (int o = 16; o; o >>= 1) sm[k] += __shfl_down_sync(FULLMASK, sm[k], o);
        if (lane == 0) s_red[k][warp] = sm[k];
    }
    __syncthreads();
    if (t < 12) {
        double tot = 0.0;
        for (int w = 0; w < 8; w++) tot += (double)s_red[t][w];
        atomicAdd(&g_ch[t], tot);
    }
}

// =====================================================================
// K3b: cdist with on-the-fly BN1 normalize+relu. 16 blocks (one per
// batch) x 512 threads; warp per channel-pair.
// =====================================================================
__global__ void __launch_bounds__(512) finalize2_kernel(
    const float* __restrict__ bn1g, const float* __restrict__ bn1b)
{
    const int b = blockIdx.x;
    const int t = threadIdx.x, lane = t & 31, warp = t >> 5;

    if (t < 6) g_tf[b * 36 + t * 7] = 0.0f;      // diagonal

    if (warp < 15) {
        int i = 0, j = 0, p = warp;
        for (i = 0; i < 5; i++) {
            int row = 5 - i;
            if (p < row) { j = i + 1 + p; break; }
            p -= row;
        }
        const double Ninv = 1.0 / (double)(BB * SS);
        double mid = g_ch[i] * Ninv;
        double vid = g_ch[6 + i] * Ninv - mid * mid;   // biased var
        double mjd = g_ch[j] * Ninv;
        double vjd = g_ch[6 + j] * Ninv - mjd * mjd;
        float mi = (float)mid, di = (float)sqrt(vid + 1e-5);
        float mj = (float)mjd, dj = (float)sqrt(vjd + 1e-5);
        float gi = bn1g[i], bi = bn1b[i];
        float gj = bn1g[j], bj = bn1b[j];

        const float* A  = g_lc + (b * 6 + i) * SS;
        const float* Bp = g_lc + (b * 6 + j) * SS;
        float part = 0.0f;
        for (int s = lane; s < SS; s += 32) {
            float a = fmaxf((A[s] - mi) / di * gi + bi, 0.0f);
            float c = fmaxf((Bp[s] - mj) / dj * gj + bj, 0.0f);
            float d = a - c;
            part += d * d;
        }
#pragma unroll
        for (int o = 16; o; o >>= 1) part += __shfl_down_sync(FULLMASK, part, o);
        if (lane == 0) {
            float v = part > 0.0f ? sqrtf(part) : 0.0f;   // zero-safe
            g_tf[b * 36 + i * 6 + j] = v;
            g_tf[b * 36 + j * 6 + i] = v;
        }
    }
}

// =====================================================================
// K3c: BN2 + output; resets pipeline state for the next replay.
// =====================================================================
__global__ void __launch_bounds__(1024) finalize3_kernel(
    const float* __restrict__ bn2g, const float* __restrict__ bn2b,
    float* __restrict__ out)
{
    const int t = threadIdx.x;
    __shared__ float s_m[36], s_v[36];

    if (t < 36) {
        float m = 0.0f;
        for (int b = 0; b < BB; b++) m += g_tf[b * 36 + t];
        m /= (float)BB;
        float v = 0.0f;
        for (int b = 0; b < BB; b++) {
            float d = g_tf[b * 36 + t] - m;
            v += d * d;
        }
        v /= (float)BB;
        s_m[t] = m; s_v[t] = v;
    }
    __syncthreads();
    if (t < BB * 36) {
        int f = t % 36;
        float x = g_tf[t];
        float y = (x - s_m[f]) / sqrtf(s_v[f] + 1e-5f) * bn2g[f] + bn2b[f];
        out[t] = fmaxf(y, 0.0f);
    }
    // reset pipeline state for next replay (first-ever run: zero-init)
    if (t >= 1000 && t < 1000 + BB) g_prog[t - 1000] = 0;
    if (t >= 960 && t < 972) g_ch[t - 960] = 0.0;
    if (t == 959) { g_acc[0] = 0.0; g_acc[1] = 0.0; }
}

// =====================================================================
extern "C" void kernel_launch(void* const* d_in, const int* in_sizes, int n_in,
                              void* d_out, int out_size)
{
    const float* xyz  = (const float*)d_in[0];
    const float* bn1g = (const float*)d_in[1];
    const float* bn1b = (const float*)d_in[2];
    const float* bn2g = (const float*)d_in[3];
    const float* bn2b = (const float*)d_in[4];
    float* out = (float*)d_out;

    // idempotent host-side attribute set (capture-safe)
    cudaFuncSetAttribute(fused_kernel, cudaFuncAttributeMaxDynamicSharedMemorySize,
                         NN * 16);

    fused_kernel<<<BB + BB * 8, 1024, NN * 16>>>(xyz);     // 144 blocks
    finalize1_kernel<<<64, 256>>>();
    finalize2_kernel<<<BB, 512>>>(bn1g, bn1b);
    finalize3_kernel<<<1, 1024>>>(bn2g, bn2b, out);
}

// round 12
// speedup vs baseline: 1.7107x; 1.1302x over previous
#include <cuda_runtime.h>
#include <cuda_bf16.h>

#define BB 16
#define NN 8192
#define SS 1024
#define KK 32
#define FULLMASK 0xFFFFFFFFu
typedef unsigned long long ull;

// ---------------- scratch (no allocs allowed) ----------------
__device__ float  g_newxyz[BB * SS * 3];   // FPS-selected centers
__device__ float  g_gmax[BB * SS * 3];     // max over K of diff, per coord
__device__ float  g_gsum[BB * SS * 3];     // sum over K of diff, per coord
__device__ double g_acc[2];                // sum(diff), sum(diff^2) for global std
__device__ float  g_lc[BB * 6 * SS];       // pooled features (raw, pre-BN1)
__device__ int    g_prog[BB * 32];         // progress, one 128B line per batch
__device__ double g_ch[12];                // BN1 per-channel sum[6], sumsq[6]
__device__ float  g_tf[BB * 36];           // cdist features pre-BN2

// ---------------- f32x2 helpers (Blackwell packed fp32) ----------------
__device__ __forceinline__ ull pk2(float lo, float hi) {
    ull r;
    asm("mov.b64 %0, {%1, %2};" : "=l"(r) : "f"(lo), "f"(hi));
    return r;
}
__device__ __forceinline__ void upk2(float& lo, float& hi, ull v) {
    asm("mov.b64 {%0, %1}, %2;" : "=f"(lo), "=f"(hi) : "l"(v));
}
__device__ __forceinline__ ull add2(ull a, ull b) {
    ull r;
    asm("add.rn.f32x2 %0, %1, %2;" : "=l"(r) : "l"(a), "l"(b));
    return r;
}
__device__ __forceinline__ ull mul2(ull a, ull b) {
    ull r;
    asm("mul.rn.f32x2 %0, %1, %2;" : "=l"(r) : "l"(a), "l"(b));
    return r;
}

// ---------------- release/acquire progress channel ----------------
__device__ __forceinline__ void st_rel_gpu(int* p, int v) {
    asm volatile("st.release.gpu.s32 [%0], %1;" :: "l"(p), "r"(v) : "memory");
}
__device__ __forceinline__ int ld_acq_gpu(const int* p) {
    int v;
    asm volatile("ld.acquire.gpu.s32 %0, [%1];" : "=r"(v) : "l"(p) : "memory");
    return v;
}

// ---------------- top-k machinery (R9, proven) ----------------
__device__ __forceinline__ ull u64min(ull a, ull b) { return a < b ? a : b; }
__device__ __forceinline__ ull u64max(ull a, ull b) { return a < b ? b : a; }
__device__ __forceinline__ ull makekey(float d, int idx) {
    unsigned ub = __float_as_uint(d);
    ub ^= ((unsigned)((int)ub >> 31)) | 0x80000000u;
    return ((ull)ub << 13) | (unsigned)idx;
}
__device__ __forceinline__ float kth2kd(ull kth) {
    unsigned ub = (unsigned)(kth >> 13);
    unsigned db = (ub >> 31) ? (ub ^ 0x80000000u) : ~ub;
    return __uint_as_float(db);
}
__device__ __forceinline__ ull sort32(ull key, int lane)
{
#pragma unroll
    for (int k = 2; k <= 32; k <<= 1) {
#pragma unroll
        for (int j = k >> 1; j > 0; j >>= 1) {
            ull other = __shfl_xor_sync(FULLMASK, key, j);
            bool up = ((lane & k) == 0);
            bool takeMin = (((lane & j) == 0) == up);
            key = takeMin ? u64min(key, other) : u64max(key, other);
        }
    }
    return key;
}
__device__ __forceinline__ ull merge32(ull key, ull buf, int lane)
{
    buf = sort32(buf, lane);
    ull rev = __shfl_sync(FULLMASK, buf, 31 - lane);
    key = u64min(key, rev);
#pragma unroll
    for (int j = 16; j > 0; j >>= 1) {
        ull other = __shfl_xor_sync(FULLMASK, key, j);
        bool takeMin = ((lane & j) == 0);
        key = takeMin ? u64min(key, other) : u64max(key, other);
    }
    return key;
}
__device__ __forceinline__ void push_chunk(ull ck, unsigned m, int lane,
                                           ull& key, float& kd,
                                           ull& buf, int& bcnt)
{
    int cnt = __popc(m);
    int r = lane - bcnt;
    bool take = (r >= 0) && (r < cnt);
    unsigned pos = __fns(m, 0, take ? (r + 1) : 1);
    ull got = __shfl_sync(FULLMASK, ck, pos & 31);
    if (take) buf = got;
    bcnt += cnt;
    if (bcnt >= 32) {
        key = merge32(key, buf, lane);
        ull kth = __shfl_sync(FULLMASK, key, 31);
        kd = kth2kd(kth);
        int left = bcnt - 32;
        buf = ~0ull;
        if (left) {   // re-push overflow candidates (extras are harmless)
            int start = cnt - left;
            bool tk2 = lane < left;
            unsigned pos2 = __fns(m, 0, tk2 ? (start + lane + 1) : 1);
            ull got2 = __shfl_sync(FULLMASK, ck, pos2 & 31);
            if (tk2) buf = got2;
        }
        bcnt = left;
    }
}

// =====================================================================
// Fused producer/consumer kernel. 144 blocks x 1024 threads (all
// resident in wave 1 on 148 SMs -> spin-wait is deadlock-free).
//   blocks 0..15   : FPS for batch b (exact R4 math), publishes
//                    g_prog[b*32] every 16 steps via st.release.gpu.
//   blocks 16..143 : kNN (R9 pairing); warps wait via ld.acquire.gpu
//                    with 2us-backoff polling (publish period ~15us).
// Results are bit-identical to the sequential version.
// =====================================================================
__global__ void __launch_bounds__(1024) fused_kernel(const float* __restrict__ xyz)
{
    extern __shared__ char dyn_smem[];
    const int t = threadIdx.x;
    const int lane = t & 31, warp = t >> 5;

    if (blockIdx.x < BB) {
        // ---------------- FPS path ----------------
        const int b = blockIdx.x;
        const float* X = xyz + (size_t)b * NN * 3;

        ull px2[4], py2[4], pz2[4];
        float dist[8];
#pragma unroll
        for (int i = 0; i < 4; i++) {
            int p0 = t + 1024 * (2 * i);
            int p1 = t + 1024 * (2 * i + 1);
            px2[i] = pk2(X[p0 * 3 + 0], X[p1 * 3 + 0]);
            py2[i] = pk2(X[p0 * 3 + 1], X[p1 * 3 + 1]);
            pz2[i] = pk2(X[p0 * 3 + 2], X[p1 * 3 + 2]);
            dist[2 * i] = 1e10f;
            dist[2 * i + 1] = 1e10f;
        }

        __shared__ unsigned s_val[2][32];
        __shared__ int      s_idx[2][32];

        float cx = X[0], cy = X[1], cz = X[2];   // sample 0 = point 0
        if (t == 0) {
            float* o = g_newxyz + (size_t)(b * SS) * 3;
            o[0] = cx; o[1] = cy; o[2] = cz;
        }

        for (int s = 0; s < SS - 1; s++) {
            const ull ncx2 = pk2(-cx, -cx);
            const ull ncy2 = pk2(-cy, -cy);
            const ull ncz2 = pk2(-cz, -cz);

            float bestv = -1.0f;
#pragma unroll
            for (int i = 0; i < 4; i++) {
                ull dx2 = add2(px2[i], ncx2);
                ull dy2 = add2(py2[i], ncy2);
                ull dz2 = add2(pz2[i], ncz2);
                ull d2 = add2(add2(mul2(dx2, dx2), mul2(dy2, dy2)), mul2(dz2, dz2));
                float d0, d1;
                upk2(d0, d1, d2);
                float n0 = fminf(dist[2 * i], d0);
                float n1 = fminf(dist[2 * i + 1], d1);
                dist[2 * i] = n0;
                dist[2 * i + 1] = n1;
                bestv = fmaxf(bestv, fmaxf(n0, n1));
            }

            unsigned wm = __reduce_max_sync(FULLMASK, __float_as_uint(bestv));
            float wmf = __uint_as_float(wm);
            unsigned cand = 0x7FFFFFFFu;
#pragma unroll
            for (int sl = 7; sl >= 0; sl--)
                cand = (dist[sl] == wmf) ? (unsigned)(t + (sl << 10)) : cand;
            cand = __reduce_min_sync(FULLMASK, cand);

            if (lane == 0) { s_val[s & 1][warp] = wm; s_idx[s & 1][warp] = (int)cand; }
            __syncthreads();

            unsigned v = s_val[s & 1][lane];
            int      ci = s_idx[s & 1][lane];
            unsigned gm = __reduce_max_sync(FULLMASK, v);
            unsigned c2 = (v == gm) ? (unsigned)ci : 0x7FFFFFFFu;
            int widx = (int)__reduce_min_sync(FULLMASK, c2);

            cx = X[widx * 3 + 0];
            cy = X[widx * 3 + 1];
            cz = X[widx * 3 + 2];
            if (t == 0) {
                float* o = g_newxyz + (size_t)(b * SS + s + 1) * 3;
                o[0] = cx; o[1] = cy; o[2] = cz;
                if ((s & 15) == 15)             // publish progress (release)
                    st_rel_gpu(&g_prog[b * 32], s + 2);
            }
        }
        if (t == 0) st_rel_gpu(&g_prog[b * 32], SS);   // final publish
        return;
    }

    // ---------------- kNN path ----------------
    ulonglong2* sxy = (ulonglong2*)dyn_smem;          // [NN/2] {x2, y2}
    ulonglong2* szw = (ulonglong2*)dyn_smem + NN / 2; // [NN/2] {z2, sq2}
    __shared__ double s_p1[32], s_p2[32];

    const int kb = blockIdx.x - BB;
    const int b  = kb >> 3;                    // 8 blocks per batch
    const int qc = kb & 7;
    const float* X = xyz + (size_t)b * NN * 3;

    for (int j = t; j < NN / 2; j += 1024) {
        const float* p = X + 6 * j;
        float x0 = p[0], y0 = p[1], z0 = p[2];
        float x1 = p[3], y1 = p[4], z1 = p[5];
        float sq0 = __fadd_rn(__fadd_rn(__fmul_rn(x0, x0), __fmul_rn(y0, y0)),
                              __fmul_rn(z0, z0));
        float sq1 = __fadd_rn(__fadd_rn(__fmul_rn(x1, x1), __fmul_rn(y1, y1)),
                              __fmul_rn(z1, z1));
        sxy[j] = make_ulonglong2(pk2(x0, x1), pk2(y0, y1));
        szw[j] = make_ulonglong2(pk2(z0, z1), pk2(sq0, sq1));
    }
    __syncthreads();

    const ull m2two = pk2(-2.0f, -2.0f);
    const int g = qc * 32 + warp;              // 0..255 per batch

    double acc1 = 0.0, acc2 = 0.0;             // meaningful on lane 0 only

    for (int qp = 0; qp < 2; qp++) {
        const int s0 = (qp ? 512 : 0) + 2 * g;
        const int s1 = s0 + 1;

        // wait for fps to publish centroids s0, s1 (acquire; 2us backoff)
        if (ld_acq_gpu(&g_prog[b * 32]) < s1 + 1) {
            do { __nanosleep(2000); } while (ld_acq_gpu(&g_prog[b * 32]) < s1 + 1);
        }

        const float* cen0 = g_newxyz + (size_t)(b * SS + s0) * 3;
        const float* cen1 = g_newxyz + (size_t)(b * SS + s1) * 3;
        const float ax = cen0[0], ay = cen0[1], az = cen0[2];
        const float bx = cen1[0], by = cen1[1], bz = cen1[2];
        const float asq = __fadd_rn(__fadd_rn(__fmul_rn(ax, ax), __fmul_rn(ay, ay)),
                                    __fmul_rn(az, az));
        const float bsq = __fadd_rn(__fadd_rn(__fmul_rn(bx, bx), __fmul_rn(by, by)),
                                    __fmul_rn(bz, bz));
        const ull aX2 = pk2(ax, ax), aY2 = pk2(ay, ay), aZ2 = pk2(az, az);
        const ull aS2 = pk2(asq, asq);
        const ull bX2 = pk2(bx, bx), bY2 = pk2(by, by), bZ2 = pk2(bz, bz);
        const ull bS2 = pk2(bsq, bsq);

        ull key0, key1;
        float kd0, kd1;
        {
            ulonglong2 A = sxy[lane];
            ulonglong2 B = szw[lane];
            ull dot0 = add2(add2(mul2(A.x, aX2), mul2(A.y, aY2)), mul2(B.x, aZ2));
            ull dd0 = add2(add2(mul2(m2two, dot0), aS2), B.y);
            ull dot1 = add2(add2(mul2(A.x, bX2), mul2(A.y, bY2)), mul2(B.x, bZ2));
            ull dd1 = add2(add2(mul2(m2two, dot1), bS2), B.y);
            float de, dq;
            upk2(de, dq, dd0);
            key0 = sort32(makekey(de, 2 * lane), lane);
            key0 = merge32(key0, makekey(dq, 2 * lane + 1), lane);
            kd0 = kth2kd(__shfl_sync(FULLMASK, key0, 31));
            upk2(de, dq, dd1);
            key1 = sort32(makekey(de, 2 * lane), lane);
            key1 = merge32(key1, makekey(dq, 2 * lane + 1), lane);
            kd1 = kth2kd(__shfl_sync(FULLMASK, key1, 31));
        }
        ull buf0 = ~0ull, buf1 = ~0ull;
        int bc0 = 0, bc1 = 0;

        for (int jb = 32; jb < NN / 2; jb += 32) {
            const int j = jb + lane;           // cands 2j, 2j+1
            ulonglong2 A = sxy[j];
            ulonglong2 B = szw[j];
            ull dot0 = add2(add2(mul2(A.x, aX2), mul2(A.y, aY2)), mul2(B.x, aZ2));
            ull dd0 = add2(add2(mul2(m2two, dot0), aS2), B.y);
            ull dot1 = add2(add2(mul2(A.x, bX2), mul2(A.y, bY2)), mul2(B.x, bZ2));
            ull dd1 = add2(add2(mul2(m2two, dot1), bS2), B.y);
            float d0e, d0o, d1e, d1o;
            upk2(d0e, d0o, dd0);
            upk2(d1e, d1o, dd1);
            bool hit = (d0e <= kd0) | (d0o <= kd0) | (d1e <= kd1) | (d1o <= kd1);
            if (__any_sync(FULLMASK, hit)) {
                unsigned m;
                m = __ballot_sync(FULLMASK, d0e <= kd0);
                if (m) push_chunk(makekey(d0e, 2 * j), m, lane, key0, kd0, buf0, bc0);
                m = __ballot_sync(FULLMASK, d0o <= kd0);
                if (m) push_chunk(makekey(d0o, 2 * j + 1), m, lane, key0, kd0, buf0, bc0);
                m = __ballot_sync(FULLMASK, d1e <= kd1);
                if (m) push_chunk(makekey(d1e, 2 * j), m, lane, key1, kd1, buf1, bc1);
                m = __ballot_sync(FULLMASK, d1o <= kd1);
                if (m) push_chunk(makekey(d1o, 2 * j + 1), m, lane, key1, kd1, buf1, bc1);
            }
        }
        if (bc0 > 0) key0 = merge32(key0, buf0, lane);
        if (bc1 > 0) key1 = merge32(key1, buf1, lane);

        // ----- group stats for both queries -----
#pragma unroll
        for (int q = 0; q < 2; q++) {
            ull key = q ? key1 : key0;
            float cx = q ? bx : ax, cy = q ? by : ay, cz = q ? bz : az;
            int sq = q ? s1 : s0;
            int ki = (int)(key & 0x1FFFull);
            ulonglong2 P1 = sxy[ki >> 1];
            ulonglong2 P2 = szw[ki >> 1];
            float xl, xh, yl, yh, zl, zh;
            upk2(xl, xh, P1.x);
            upk2(yl, yh, P1.y);
            upk2(zl, zh, P2.x);
            float px = (ki & 1) ? xh : xl;
            float py = (ki & 1) ? yh : yl;
            float pz = (ki & 1) ? zh : zl;
            float dx = __fsub_rn(px, cx);
            float dy = __fsub_rn(py, cy);
            float dz = __fsub_rn(pz, cz);
            float sdx = dx, sdy = dy, sdz = dz;
            float mdx = dx, mdy = dy, mdz = dz;
            float t1 = dx + dy + dz;
            float t2 = dx * dx + dy * dy + dz * dz;
#pragma unroll
            for (int o = 16; o; o >>= 1) {
                sdx += __shfl_down_sync(FULLMASK, sdx, o);
                sdy += __shfl_down_sync(FULLMASK, sdy, o);
                sdz += __shfl_down_sync(FULLMASK, sdz, o);
                mdx = fmaxf(mdx, __shfl_down_sync(FULLMASK, mdx, o));
                mdy = fmaxf(mdy, __shfl_down_sync(FULLMASK, mdy, o));
                mdz = fmaxf(mdz, __shfl_down_sync(FULLMASK, mdz, o));
                t1 += __shfl_down_sync(FULLMASK, t1, o);
                t2 += __shfl_down_sync(FULLMASK, t2, o);
            }
            if (lane == 0) {
                int ix = (b * SS + sq) * 3;
                g_gsum[ix] = sdx; g_gsum[ix + 1] = sdy; g_gsum[ix + 2] = sdz;
                g_gmax[ix] = mdx; g_gmax[ix + 1] = mdy; g_gmax[ix + 2] = mdz;
                acc1 += (double)t1;
                acc2 += (double)t2;
            }
        }
    }

    if (lane == 0) { s_p1[warp] = acc1; s_p2[warp] = acc2; }
    __syncthreads();
    if (t == 0) {
        double a = 0.0, c = 0.0;
        for (int w = 0; w < 32; w++) { a += s_p1[w]; c += s_p2[w]; }
        atomicAdd(&g_acc[0], a);
        atomicAdd(&g_acc[1], c);
    }
}

// =====================================================================
// K3a: lc build (64 blocks) + BN1 channel sum/sumsq via double atomics.
// =====================================================================
__global__ void __launch_bounds__(256) finalize1_kernel()
{
    const int t = threadIdx.x;
    const int lane = t & 31, warp = t >> 5;
    const int idx = blockIdx.x * 256 + t;     // 0..16383
    __shared__ float s_red[12][8];

    double M = (double)BB * SS * KK * 3;
    double var = (g_acc[1] - g_acc[0] * g_acc[0] / M) / (M - 1.0);  // ddof=1
    const float se = (float)sqrt(var) + 1e-5f;

    int b = idx >> 10, s = idx & (SS - 1);
    const float* gm = g_gmax + idx * 3;
    const float* gs = g_gsum + idx * 3;
    const float* cn = g_newxyz + idx * 3;
    float v[6];
#pragma unroll
    for (int c = 0; c < 3; c++) {
        float mx = __fdiv_rn(gm[c], se);
        float mn = __fdiv_rn(__fdiv_rn(gs[c], 32.0f), se);
        v[c] = __fadd_rn(mx, mn);
        g_lc[(b * 6 + c) * SS + s] = v[c];
    }
#pragma unroll
    for (int c = 0; c < 3; c++) {
        float w = cn[c];
        v[3 + c] = w + w;
        g_lc[(b * 6 + 3 + c) * SS + s] = v[3 + c];
    }

    float sm[12];
#pragma unroll
    for (int c = 0; c < 6; c++) { sm[c] = v[c]; sm[6 + c] = v[c] * v[c]; }
#pragma unroll
    for (int k = 0; k < 12; k++) {
#pragma unroll
        for (int o = 16; o; o >>= 1) sm[k] += __shfl_down_sync(FULLMASK, sm[k], o);
        if (lane == 0) s_red[k][warp] = sm[k];
    }
    __syncthreads();
    if (t < 12) {
        double tot = 0.0;
        for (int w = 0; w < 8; w++) tot += (double)s_red[t][w];
        atomicAdd(&g_ch[t], tot);
    }
}

// =====================================================================
// K3b: cdist with on-the-fly BN1 normalize+relu. 16 blocks (one per
// batch) x 512 threads; warp per channel-pair.
// =====================================================================
__global__ void __launch_bounds__(512) finalize2_kernel(
    const float* __restrict__ bn1g, const float* __restrict__ bn1b)
{
    const int b = blockIdx.x;
    const int t = threadIdx.x, lane = t & 31, warp = t >> 5;

    if (t < 6) g_tf[b * 36 + t * 7] = 0.0f;      // diagonal

    if (warp < 15) {
        int i = 0, j = 0, p = warp;
        for (i = 0; i < 5; i++) {
            int row = 5 - i;
            if (p < row) { j = i + 1 + p; break; }
            p -= row;
        }
        const double Ninv = 1.0 / (double)(BB * SS);
        double mid = g_ch[i] * Ninv;
        double vid = g_ch[6 + i] * Ninv - mid * mid;   // biased var
        double mjd = g_ch[j] * Ninv;
        double vjd = g_ch[6 + j] * Ninv - mjd * mjd;
        float mi = (float)mid, di = (float)sqrt(vid + 1e-5);
        float mj = (float)mjd, dj = (float)sqrt(vjd + 1e-5);
        float gi = bn1g[i], bi = bn1b[i];
        float gj = bn1g[j], bj = bn1b[j];

        const float* A  = g_lc + (b * 6 + i) * SS;
        const float* Bp = g_lc + (b * 6 + j) * SS;
        float part = 0.0f;
        for (int s = lane; s < SS; s += 32) {
            float a = fmaxf((A[s] - mi) / di * gi + bi, 0.0f);
            float c = fmaxf((Bp[s] - mj) / dj * gj + bj, 0.0f);
            float d = a - c;
            part += d * d;
        }
#pragma unroll
        for (int o = 16; o; o >>= 1) part += __shfl_down_sync(FULLMASK, part, o);
        if (lane == 0) {
            float v = part > 0.0f ? sqrtf(part) : 0.0f;   // zero-safe
            g_tf[b * 36 + i * 6 + j] = v;
            g_tf[b * 36 + j * 6 + i] = v;
        }
    }
}

// =====================================================================
// K3c: BN2 + output; resets pipeline state for the next replay.
// =====================================================================
__global__ void __launch_bounds__(1024) finalize3_kernel(
    const float* __restrict__ bn2g, const float* __restrict__ bn2b,
    float* __restrict__ out)
{
    const int t = threadIdx.x;
    __shared__ float s_m[36], s_v[36];

    if (t < 36) {
        float m = 0.0f;
        for (int b = 0; b < BB; b++) m += g_tf[b * 36 + t];
        m /= (float)BB;
        float v = 0.0f;
        for (int b = 0; b < BB; b++) {
            float d = g_tf[b * 36 + t] - m;
            v += d * d;
        }
        v /= (float)BB;
        s_m[t] = m; s_v[t] = v;
    }
    __syncthreads();
    if (t < BB * 36) {
        int f = t % 36;
        float x = g_tf[t];
        float y = (x - s_m[f]) / sqrtf(s_v[f] + 1e-5f) * bn2g[f] + bn2b[f];
        out[t] = fmaxf(y, 0.0f);
    }
    // reset pipeline state for next replay (first-ever run: zero-init)
    if (t >= 512 && t < 512 + BB * 32) g_prog[t - 512] = 0;
    if (t >= 96 && t < 108) g_ch[t - 96] = 0.0;
    if (t == 95) { g_acc[0] = 0.0; g_acc[1] = 0.0; }
}

// =====================================================================
extern "C" void kernel_launch(void* const* d_in, const int* in_sizes, int n_in,
                              void* d_out, int out_size)
{
    const float* xyz  = (const float*)d_in[0];
    const float* bn1g = (const float*)d_in[1];
    const float* bn1b = (const float*)d_in[2];
    const float* bn2g = (const float*)d_in[3];
    const float* bn2b = (const float*)d_in[4];
    float* out = (float*)d_out;

    // idempotent host-side attribute set (capture-safe)
    cudaFuncSetAttribute(fused_kernel, cudaFuncAttributeMaxDynamicSharedMemorySize,
                         NN * 16);

    fused_kernel<<<BB + BB * 8, 1024, NN * 16>>>(xyz);     // 144 blocks
    finalize1_kernel<<<64, 256>>>();
    finalize2_kernel<<<BB, 512>>>(bn1g, bn1b);
    finalize3_kernel<<<1, 1024>>>(bn2g, bn2b, out);
}